// round 9
// baseline (speedup 1.0000x reference)
#include <cuda_runtime.h>
#include <math.h>

// ---------------- problem constants ----------------
#define BATCH 4
#define NTOK  2048
#define N1    2049          // tokens + cls
#define DIN   768
#define DIM   512
#define H3    1536          // 3*H*DH
#define DEPTH 2
#define ROWS_TOT (BATCH * N1)   // 8196
#define ATT_SCALE 0.125f        // 64^-0.5

// ---------------- scratch (device globals; allocation-free) ----------------
__device__ __align__(256) float g_x  [BATCH * N1 * DIM];   // running activations
__device__ __align__(256) float g_xn [BATCH * N1 * DIM];   // LN output
__device__ __align__(256) float g_qkv[BATCH * N1 * H3];    // qkv projections
__device__ __align__(256) float g_o  [BATCH * N1 * DIM];   // attention output
__device__ __align__(256) float g_h  [BATCH * N1 * DIM];   // mlp hidden

// ---------------- tiny helpers ----------------
__device__ __forceinline__ float gelu_exact(float v) {
    return 0.5f * v * (1.0f + erff(v * 0.70710678118654752440f));
}

// ---------------- cls token fill ----------------
__global__ void cls_fill_kernel(const float* __restrict__ cls, float* __restrict__ x) {
    // grid = BATCH, block = DIM
    x[(size_t)blockIdx.x * N1 * DIM + threadIdx.x] = cls[threadIdx.x];
}

// ---------------- generic SGEMM with fused epilogue ----------------
// C[M,N] = A[M,K] @ B[K,N]  (row-major), epilogue per `mode`:
//   0: none   1: +bias   2: gelu(.+bias)   3: +bias+residual
// remap: output row r -> r + r/2048 + 1  (insert cls row per batch; fc only)
// Block tile 128x64, K-tile 16, 256 threads, 8x4 per-thread micro-tile.
__global__ __launch_bounds__(256) void sgemm_ep(
    const float* __restrict__ A, const float* __restrict__ B,
    const float* __restrict__ bias, const float* __restrict__ res,
    float* __restrict__ C, int M, int N, int K, int mode, int remap)
{
    __shared__ float As[16][128];   // transposed A tile
    __shared__ float Bs[16][64];

    const int tid  = threadIdx.x;
    const int tx   = tid & 15;      // 16 col-groups
    const int ty   = tid >> 4;      // 16 row-groups
    const int row0 = blockIdx.y * 128;
    const int col0 = blockIdx.x * 64;

    // load mappings
    const int a_r = tid >> 1;            // 0..127
    const int a_k = (tid & 1) << 3;      // 0 or 8
    const int b_r = tid >> 4;            // 0..15
    const int b_c = (tid & 15) << 2;     // 0..60

    float acc[8][4];
#pragma unroll
    for (int i = 0; i < 8; i++)
#pragma unroll
        for (int j = 0; j < 4; j++) acc[i][j] = 0.f;

    const int grow = row0 + a_r;
    const bool arow_ok = (grow < M);
    const float* aptr = A + (size_t)grow * K + a_k;
    const float* bptr = B + (size_t)b_r * N + col0 + b_c;

    for (int k0 = 0; k0 < K; k0 += 16) {
        if (arow_ok) {
            float4 v0 = *(const float4*)(aptr + k0);
            float4 v1 = *(const float4*)(aptr + k0 + 4);
            As[a_k + 0][a_r] = v0.x; As[a_k + 1][a_r] = v0.y;
            As[a_k + 2][a_r] = v0.z; As[a_k + 3][a_r] = v0.w;
            As[a_k + 4][a_r] = v1.x; As[a_k + 5][a_r] = v1.y;
            As[a_k + 6][a_r] = v1.z; As[a_k + 7][a_r] = v1.w;
        } else {
#pragma unroll
            for (int i = 0; i < 8; i++) As[a_k + i][a_r] = 0.f;
        }
        float4 bv = *(const float4*)(bptr + (size_t)k0 * N);
        *(float4*)&Bs[b_r][b_c] = bv;
        __syncthreads();

#pragma unroll
        for (int kk = 0; kk < 16; kk++) {
            float ra[8];
#pragma unroll
            for (int i = 0; i < 8; i++) ra[i] = As[kk][(ty << 3) + i];
            float4 b4 = *(const float4*)&Bs[kk][tx << 2];
#pragma unroll
            for (int i = 0; i < 8; i++) {
                acc[i][0] += ra[i] * b4.x;
                acc[i][1] += ra[i] * b4.y;
                acc[i][2] += ra[i] * b4.z;
                acc[i][3] += ra[i] * b4.w;
            }
        }
        __syncthreads();
    }

    float bload[4] = {0.f, 0.f, 0.f, 0.f};
    if (mode >= 1) {
#pragma unroll
        for (int j = 0; j < 4; j++) bload[j] = bias[col0 + (tx << 2) + j];
    }

#pragma unroll
    for (int i = 0; i < 8; i++) {
        int r = row0 + (ty << 3) + i;
        if (r >= M) continue;
        size_t orow = remap ? (size_t)(r + r / 2048 + 1) : (size_t)r;
        float* cp = C + orow * N + col0 + (tx << 2);
        const float* rp = (mode == 3) ? (res + orow * N + col0 + (tx << 2)) : nullptr;
#pragma unroll
        for (int j = 0; j < 4; j++) {
            float vv = acc[i][j];
            if (mode >= 1) vv += bload[j];
            if (mode == 2) vv = gelu_exact(vv);
            if (mode == 3) vv += rp[j];
            cp[j] = vv;
        }
    }
}

// ---------------- LayerNorm (one block per row, D=512) ----------------
__global__ __launch_bounds__(256) void ln_kernel(
    const float* __restrict__ x, const float* __restrict__ g,
    const float* __restrict__ b, float* __restrict__ y)
{
    const int row = blockIdx.x;
    const float* xr = x + (size_t)row * DIM;
    float v[2];
    float s = 0.f, s2 = 0.f;
#pragma unroll
    for (int it = 0; it < 2; it++) {
        v[it] = xr[threadIdx.x + it * 256];
        s += v[it]; s2 += v[it] * v[it];
    }
#pragma unroll
    for (int off = 16; off; off >>= 1) {
        s  += __shfl_xor_sync(0xffffffffu, s,  off);
        s2 += __shfl_xor_sync(0xffffffffu, s2, off);
    }
    __shared__ float rs[8], rs2[8];
    __shared__ float smean, srstd;
    const int w = threadIdx.x >> 5;
    if ((threadIdx.x & 31) == 0) { rs[w] = s; rs2[w] = s2; }
    __syncthreads();
    if (threadIdx.x == 0) {
        float a = 0.f, a2 = 0.f;
        for (int i = 0; i < 8; i++) { a += rs[i]; a2 += rs2[i]; }
        float mean = a * (1.f / DIM);
        float var  = a2 * (1.f / DIM) - mean * mean;
        smean = mean;
        srstd = rsqrtf(var + 1e-5f);
    }
    __syncthreads();
    const float mean = smean, rstd = srstd;
#pragma unroll
    for (int it = 0; it < 2; it++) {
        int c = threadIdx.x + it * 256;
        y[(size_t)row * DIM + c] = (v[it] - mean) * rstd * g[c] + b[c];
    }
}

// ---------------- fused flash-style attention ----------------
// grid = (33 q-tiles, 8 heads, 4 batch), block = 256
// qkv layout: [b, i, 3*H*DH]; Q at col h*64, K at 512+h*64, V at 1024+h*64
__global__ __launch_bounds__(256) void attn_kernel(
    const float* __restrict__ qkv, const int* __restrict__ lens,
    float* __restrict__ o)
{
    const int qt  = blockIdx.x;
    const int h   = blockIdx.y;
    const int b   = blockIdx.z;
    const int tid = threadIdx.x;
    const int len1 = lens[b] + 1;
    const int qbase = qt * 64;

    __shared__ float Qs [64][65];
    __shared__ float Kst[64][33];   // transposed: [d][k]
    __shared__ float Vs [32][65];
    __shared__ float Ss [64][33];
    __shared__ float m_s[64], l_s[64], f_s[64];

    // ---- load Q tile ----
    {
        const int q  = tid >> 2;
        const int d0 = (tid & 3) << 4;
        const int qg = qbase + q;
        if (qg < N1) {
            const float* src = qkv + ((size_t)(b * N1 + qg) * H3 + h * 64 + d0);
#pragma unroll
            for (int i = 0; i < 16; i += 4) {
                float4 v4 = *(const float4*)(src + i);
                Qs[q][d0 + i + 0] = v4.x; Qs[q][d0 + i + 1] = v4.y;
                Qs[q][d0 + i + 2] = v4.z; Qs[q][d0 + i + 3] = v4.w;
            }
        } else {
#pragma unroll
            for (int i = 0; i < 16; i++) Qs[q][d0 + i] = 0.f;
        }
    }
    if (tid < 64) { m_s[tid] = -1e30f; l_s[tid] = 0.f; }

    const int ty = tid >> 3;        // 0..31
    const int tx = tid & 7;         // 0..7
    const int qy = ty << 1;         // query pair base
    const int kx = tx << 2;         // S col group (4)
    const int dy = tx << 3;         // O col group (8)

    float acc[2][8];
#pragma unroll
    for (int r = 0; r < 2; r++)
#pragma unroll
        for (int i = 0; i < 8; i++) acc[r][i] = 0.f;

    const bool q0pad = (qbase + qy)     >= len1;
    const bool q1pad = (qbase + qy + 1) >= len1;

    const int NT = (N1 + 31) / 32;  // 65
    for (int kt = 0; kt < NT; kt++) {
        const int kbase = kt * 32;
        __syncthreads();            // previous PV done before reloading K/V/Ss

        // ---- load K (transposed) and V tiles ----
        {
            const int k  = tid >> 3;           // 0..31
            const int d0 = (tid & 7) << 3;     // 0..56
            const int kg = kbase + k;
            if (kg < N1) {
                const float* kp = qkv + ((size_t)(b * N1 + kg) * H3 + 512 + h * 64 + d0);
                const float* vp = kp + 512;
#pragma unroll
                for (int i = 0; i < 8; i += 4) {
                    float4 k4 = *(const float4*)(kp + i);
                    Kst[d0 + i + 0][k] = k4.x; Kst[d0 + i + 1][k] = k4.y;
                    Kst[d0 + i + 2][k] = k4.z; Kst[d0 + i + 3][k] = k4.w;
                    float4 v4 = *(const float4*)(vp + i);
                    Vs[k][d0 + i + 0] = v4.x; Vs[k][d0 + i + 1] = v4.y;
                    Vs[k][d0 + i + 2] = v4.z; Vs[k][d0 + i + 3] = v4.w;
                }
            } else {
#pragma unroll
                for (int i = 0; i < 8; i++) { Kst[d0 + i][k] = 0.f; Vs[k][d0 + i] = 0.f; }
            }
        }
        __syncthreads();

        // ---- S = Q K^T (2x4 per thread) ----
        float s[2][4];
#pragma unroll
        for (int r = 0; r < 2; r++)
#pragma unroll
            for (int j = 0; j < 4; j++) s[r][j] = 0.f;
#pragma unroll
        for (int d = 0; d < 64; d++) {
            float q0 = Qs[qy][d], q1 = Qs[qy + 1][d];
            float k0 = Kst[d][kx + 0], k1 = Kst[d][kx + 1];
            float k2 = Kst[d][kx + 2], k3 = Kst[d][kx + 3];
            s[0][0] += q0 * k0; s[0][1] += q0 * k1; s[0][2] += q0 * k2; s[0][3] += q0 * k3;
            s[1][0] += q1 * k0; s[1][1] += q1 * k1; s[1][2] += q1 * k2; s[1][3] += q1 * k3;
        }
#pragma unroll
        for (int j = 0; j < 4; j++) {
            const int kg = kbase + kx + j;
            const bool kbad = (kg >= N1);
            const bool kpad = (kg >= len1);
            Ss[qy][kx + j]     = (kbad || (q0pad && kpad)) ? -1e30f : s[0][j] * ATT_SCALE;
            Ss[qy + 1][kx + j] = (kbad || (q1pad && kpad)) ? -1e30f : s[1][j] * ATT_SCALE;
        }
        __syncthreads();

        // ---- online softmax update (row per thread) ----
        if (tid < 64) {
            float mold = m_s[tid];
            float mt = -1e30f;
#pragma unroll
            for (int k = 0; k < 32; k++) mt = fmaxf(mt, Ss[tid][k]);
            float mnew = fmaxf(mold, mt);
            float fac = expf(mold - mnew);
            float ls = 0.f;
#pragma unroll
            for (int k = 0; k < 32; k++) {
                float p = expf(Ss[tid][k] - mnew);
                Ss[tid][k] = p;
                ls += p;
            }
            l_s[tid] = l_s[tid] * fac + ls;
            m_s[tid] = mnew;
            f_s[tid] = fac;
        }
        __syncthreads();

        // ---- rescale + O += P V ----
        const float f0 = f_s[qy], f1 = f_s[qy + 1];
#pragma unroll
        for (int i = 0; i < 8; i++) { acc[0][i] *= f0; acc[1][i] *= f1; }
#pragma unroll
        for (int kk = 0; kk < 32; kk++) {
            float p0 = Ss[qy][kk], p1 = Ss[qy + 1][kk];
#pragma unroll
            for (int i = 0; i < 8; i++) {
                float vv = Vs[kk][dy + i];
                acc[0][i] += p0 * vv;
                acc[1][i] += p1 * vv;
            }
        }
    }

    // ---- normalize and write O ----
    const float il0 = 1.f / l_s[qy];
    const float il1 = 1.f / l_s[qy + 1];
    const int qg0 = qbase + qy;
    if (qg0 < N1) {
        float* op = o + ((size_t)(b * N1 + qg0) * DIM + h * 64 + dy);
#pragma unroll
        for (int i = 0; i < 8; i++) op[i] = acc[0][i] * il0;
    }
    if (qg0 + 1 < N1) {
        float* op = o + ((size_t)(b * N1 + qg0 + 1) * DIM + h * 64 + dy);
#pragma unroll
        for (int i = 0; i < 8; i++) op[i] = acc[1][i] * il1;
    }
}

// ---------------- final LN + classifier head (cls token only) ----------------
__global__ __launch_bounds__(256) void head_kernel(
    const float* __restrict__ x, const float* __restrict__ g,
    const float* __restrict__ bb, const float* __restrict__ hw,
    const float* __restrict__ hb, float* __restrict__ out)
{
    const int b = blockIdx.x;
    const float* xr = x + (size_t)b * N1 * DIM;   // row 0 = cls
    float v[2];
    float s = 0.f, s2 = 0.f;
#pragma unroll
    for (int it = 0; it < 2; it++) {
        v[it] = xr[threadIdx.x + it * 256];
        s += v[it]; s2 += v[it] * v[it];
    }
#pragma unroll
    for (int off = 16; off; off >>= 1) {
        s  += __shfl_xor_sync(0xffffffffu, s,  off);
        s2 += __shfl_xor_sync(0xffffffffu, s2, off);
    }
    __shared__ float rs[8], rs2[8];
    __shared__ float smean, srstd;
    const int w = threadIdx.x >> 5;
    if ((threadIdx.x & 31) == 0) { rs[w] = s; rs2[w] = s2; }
    __syncthreads();
    if (threadIdx.x == 0) {
        float a = 0.f, a2 = 0.f;
        for (int i = 0; i < 8; i++) { a += rs[i]; a2 += rs2[i]; }
        float mean = a * (1.f / DIM);
        float var  = a2 * (1.f / DIM) - mean * mean;
        smean = mean;
        srstd = rsqrtf(var + 1e-5f);
    }
    __syncthreads();
    const float mean = smean, rstd = srstd;

    float d0 = 0.f, d1 = 0.f;
#pragma unroll
    for (int it = 0; it < 2; it++) {
        int c = threadIdx.x + it * 256;
        float xn = (v[it] - mean) * rstd * g[c] + bb[c];
        d0 += xn * hw[2 * c + 0];
        d1 += xn * hw[2 * c + 1];
    }
#pragma unroll
    for (int off = 16; off; off >>= 1) {
        d0 += __shfl_xor_sync(0xffffffffu, d0, off);
        d1 += __shfl_xor_sync(0xffffffffu, d1, off);
    }
    __syncthreads();   // reuse rs/rs2
    if ((threadIdx.x & 31) == 0) { rs[w] = d0; rs2[w] = d1; }
    __syncthreads();
    if (threadIdx.x == 0) {
        float a0 = 0.f, a1 = 0.f;
        for (int i = 0; i < 8; i++) { a0 += rs[i]; a1 += rs2[i]; }
        out[b * 2 + 0] = a0 + hb[0];
        out[b * 2 + 1] = a1 + hb[1];
    }
}

// ---------------- launch ----------------
extern "C" void kernel_launch(void* const* d_in, const int* in_sizes, int n_in,
                              void* d_out, int out_size)
{
    const float* x      = (const float*)d_in[0];
    const int*   lens   = (const int*)  d_in[1];
    const float* cls    = (const float*)d_in[2];
    const float* fc_w   = (const float*)d_in[3];
    const float* fc_b   = (const float*)d_in[4];
    const float* ln1_g  = (const float*)d_in[5];
    const float* ln1_b  = (const float*)d_in[6];
    const float* qkv_w  = (const float*)d_in[7];
    const float* out_w  = (const float*)d_in[8];
    const float* out_b  = (const float*)d_in[9];
    const float* ln2_g  = (const float*)d_in[10];
    const float* ln2_b  = (const float*)d_in[11];
    const float* ff1_w  = (const float*)d_in[12];
    const float* ff1_b  = (const float*)d_in[13];
    const float* ff2_w  = (const float*)d_in[14];
    const float* ff2_b  = (const float*)d_in[15];
    const float* lnf_g  = (const float*)d_in[16];
    const float* lnf_b  = (const float*)d_in[17];
    const float* head_w = (const float*)d_in[18];
    const float* head_b = (const float*)d_in[19];
    float* out = (float*)d_out;

    float *gx, *gxn, *gqkv, *go, *gh;
    cudaGetSymbolAddress((void**)&gx,   g_x);
    cudaGetSymbolAddress((void**)&gxn,  g_xn);
    cudaGetSymbolAddress((void**)&gqkv, g_qkv);
    cudaGetSymbolAddress((void**)&go,   g_o);
    cudaGetSymbolAddress((void**)&gh,   g_h);

    // cls rows
    cls_fill_kernel<<<BATCH, DIM>>>(cls, gx);

    // fc + GELU, remapped into cls-offset layout: M=8192, N=512, K=768
    sgemm_ep<<<dim3(DIM / 64, (BATCH * NTOK + 127) / 128), 256>>>(
        x, fc_w, fc_b, nullptr, gx, BATCH * NTOK, DIM, DIN, /*mode=*/2, /*remap=*/1);

    const int gy = (ROWS_TOT + 127) / 128;   // 65
    for (int l = 0; l < DEPTH; l++) {
        // LN1
        ln_kernel<<<ROWS_TOT, 256>>>(gx, ln1_g + l * DIM, ln1_b + l * DIM, gxn);
        // qkv projection (no bias)
        sgemm_ep<<<dim3(H3 / 64, gy), 256>>>(
            gxn, qkv_w + (size_t)l * DIM * H3, nullptr, nullptr, gqkv,
            ROWS_TOT, H3, DIM, 0, 0);
        // attention
        attn_kernel<<<dim3((N1 + 63) / 64, 8, BATCH), 256>>>(gqkv, lens, go);
        // out projection + bias + residual
        sgemm_ep<<<dim3(DIM / 64, gy), 256>>>(
            go, out_w + (size_t)l * DIM * DIM, out_b + l * DIM, gx, gx,
            ROWS_TOT, DIM, DIM, 3, 0);
        // LN2
        ln_kernel<<<ROWS_TOT, 256>>>(gx, ln2_g + l * DIM, ln2_b + l * DIM, gxn);
        // ff1 + GELU
        sgemm_ep<<<dim3(DIM / 64, gy), 256>>>(
            gxn, ff1_w + (size_t)l * DIM * DIM, ff1_b + l * DIM, nullptr, gh,
            ROWS_TOT, DIM, DIM, 2, 0);
        // ff2 + bias + residual
        sgemm_ep<<<dim3(DIM / 64, gy), 256>>>(
            gh, ff2_w + (size_t)l * DIM * DIM, ff2_b + l * DIM, gx, gx,
            ROWS_TOT, DIM, DIM, 3, 0);
    }

    // final LN (cls row only) + head
    head_kernel<<<BATCH, 256>>>(gx, lnf_g, lnf_b, head_w, head_b, out);
}

// round 10
// speedup vs baseline: 3.1391x; 3.1391x over previous
#include <cuda_runtime.h>
#include <math.h>
#include <stdint.h>

// ---------------- problem constants ----------------
#define BATCH 4
#define NTOK  2048
#define N1    2049          // tokens + cls
#define DIN   768
#define DIM   512
#define H3    1536          // 3*H*DH
#define DEPTH 2
#define ROWS_TOT (BATCH * N1)   // 8196
#define ATT_SCALE 0.125f        // 64^-0.5

// ---------------- scratch (device globals; allocation-free) ----------------
__device__ __align__(256) float g_x  [BATCH * N1 * DIM];
__device__ __align__(256) float g_xn [BATCH * N1 * DIM];
__device__ __align__(256) float g_qkv[BATCH * N1 * H3];
__device__ __align__(256) float g_o  [BATCH * N1 * DIM];
__device__ __align__(256) float g_h  [BATCH * N1 * DIM];

// ---------------- helpers ----------------
__device__ __forceinline__ float gelu_exact(float v) {
    return 0.5f * v * (1.0f + erff(v * 0.70710678118654752440f));
}

__device__ __forceinline__ uint32_t f2tf(float f) {
    uint32_t u;
    asm("cvt.rna.tf32.f32 %0, %1;" : "=r"(u) : "f"(f));
    return u;
}

// D += A(16x8,row) * B(8x8,col)  tf32, fp32 accum
__device__ __forceinline__ void mma8(float* c, const uint32_t* a, uint32_t b0, uint32_t b1) {
    asm volatile(
        "mma.sync.aligned.m16n8k8.row.col.f32.tf32.tf32.f32 "
        "{%0,%1,%2,%3}, {%4,%5,%6,%7}, {%8,%9}, {%0,%1,%2,%3};"
        : "+f"(c[0]), "+f"(c[1]), "+f"(c[2]), "+f"(c[3])
        : "r"(a[0]), "r"(a[1]), "r"(a[2]), "r"(a[3]), "r"(b0), "r"(b1));
}

// ---------------- cls token fill ----------------
__global__ void cls_fill_kernel(const float* __restrict__ cls, float* __restrict__ x) {
    x[(size_t)blockIdx.x * N1 * DIM + threadIdx.x] = cls[threadIdx.x];
}

// ---------------- TF32 tensor-core SGEMM with fused epilogue ----------------
// C[M,N] = A[M,K] @ B[K,N] (row-major). mode: 0 none, 1 +bias, 2 gelu(.+bias),
// 3 +bias+residual. remap: out row r -> r + r/2048 + 1 (cls insertion, fc only).
// Block tile 128x64x32, 8 warps as 4x2 of 32x32 warp tiles, m16n8k8 tf32 mma.
#define BM 128
#define BN 64
#define BK 32
#define AP 36   // As pitch (floats)  -> a-frag bank = 4r+j (conflict-free)
#define BP 72   // Bs pitch (floats)  -> b-frag bank = 8j+r (conflict-free)

__global__ __launch_bounds__(256, 2) void sgemm_tf32(
    const float* __restrict__ A, const float* __restrict__ B,
    const float* __restrict__ bias, const float* __restrict__ res,
    float* __restrict__ C, int M, int N, int K, int mode, int remap)
{
    __shared__ float As[BM * AP];
    __shared__ float Bs[BK * BP];

    const int tid  = threadIdx.x;
    const int lane = tid & 31;
    const int warp = tid >> 5;
    const int wm   = (warp >> 1) * 32;   // warp m offset (0,32,64,96)
    const int wn   = (warp & 1) * 32;    // warp n offset (0,32)
    const int r    = lane >> 2;          // 0..7
    const int j    = lane & 3;           // 0..3
    const int row0 = blockIdx.y * BM;
    const int col0 = blockIdx.x * BN;

    // global->smem load mapping
    const int a_r = tid >> 3;            // 0..31 (4 iters of +32)
    const int a_k = (tid & 7) * 4;       // 0..28
    const int b_k = tid >> 4;            // 0..15 (2 iters of +16)
    const int b_n = (tid & 15) * 4;      // 0..60

    float acc[2][4][4];
#pragma unroll
    for (int mt = 0; mt < 2; mt++)
#pragma unroll
        for (int nt = 0; nt < 4; nt++)
#pragma unroll
            for (int q = 0; q < 4; q++) acc[mt][nt][q] = 0.f;

    float4 pa[4], pb[2];
    // prefetch k0 = 0
#pragma unroll
    for (int i = 0; i < 4; i++) {
        int grow = row0 + i * 32 + a_r;
        pa[i] = (grow < M) ? *(const float4*)(A + (size_t)grow * K + a_k)
                           : make_float4(0.f, 0.f, 0.f, 0.f);
    }
#pragma unroll
    for (int i = 0; i < 2; i++)
        pb[i] = *(const float4*)(B + (size_t)(i * 16 + b_k) * N + col0 + b_n);

    const int KB = K / BK;
    for (int kb = 0; kb < KB; kb++) {
#pragma unroll
        for (int i = 0; i < 4; i++)
            *(float4*)&As[(i * 32 + a_r) * AP + a_k] = pa[i];
#pragma unroll
        for (int i = 0; i < 2; i++)
            *(float4*)&Bs[(i * 16 + b_k) * BP + b_n] = pb[i];
        __syncthreads();

        if (kb + 1 < KB) {
            const int k0 = (kb + 1) * BK;
#pragma unroll
            for (int i = 0; i < 4; i++) {
                int grow = row0 + i * 32 + a_r;
                pa[i] = (grow < M) ? *(const float4*)(A + (size_t)grow * K + k0 + a_k)
                                   : make_float4(0.f, 0.f, 0.f, 0.f);
            }
#pragma unroll
            for (int i = 0; i < 2; i++)
                pb[i] = *(const float4*)(B + (size_t)(k0 + i * 16 + b_k) * N + col0 + b_n);
        }

#pragma unroll
        for (int kk = 0; kk < BK; kk += 8) {
            uint32_t af[2][4];
#pragma unroll
            for (int mt = 0; mt < 2; mt++) {
                int mb = wm + mt * 16;
                af[mt][0] = f2tf(As[(mb + r    ) * AP + kk + j    ]);
                af[mt][1] = f2tf(As[(mb + r + 8) * AP + kk + j    ]);
                af[mt][2] = f2tf(As[(mb + r    ) * AP + kk + j + 4]);
                af[mt][3] = f2tf(As[(mb + r + 8) * AP + kk + j + 4]);
            }
#pragma unroll
            for (int nt = 0; nt < 4; nt++) {
                uint32_t b0 = f2tf(Bs[(kk + j    ) * BP + wn + nt * 8 + r]);
                uint32_t b1 = f2tf(Bs[(kk + j + 4) * BP + wn + nt * 8 + r]);
                mma8(acc[0][nt], af[0], b0, b1);
                mma8(acc[1][nt], af[1], b0, b1);
            }
        }
        __syncthreads();
    }

    // epilogue (c layout: c0/c1 row=r, cols 2j,2j+1; c2/c3 row=r+8)
#pragma unroll
    for (int mt = 0; mt < 2; mt++) {
#pragma unroll
        for (int half = 0; half < 2; half++) {
            int grow = row0 + wm + mt * 16 + r + half * 8;
            if (grow >= M) continue;
            size_t orow = remap ? (size_t)(grow + grow / 2048 + 1) : (size_t)grow;
#pragma unroll
            for (int nt = 0; nt < 4; nt++) {
                int gc = col0 + wn + nt * 8 + 2 * j;
                float v0 = acc[mt][nt][half * 2 + 0];
                float v1 = acc[mt][nt][half * 2 + 1];
                if (mode >= 1) { v0 += bias[gc]; v1 += bias[gc + 1]; }
                if (mode == 2) { v0 = gelu_exact(v0); v1 = gelu_exact(v1); }
                float* cp = C + orow * N + gc;
                if (mode == 3) {
                    const float* rp = res + orow * N + gc;
                    v0 += rp[0]; v1 += rp[1];
                }
                *(float2*)cp = make_float2(v0, v1);
            }
        }
    }
}

// ---------------- LayerNorm (one block per row, D=512) ----------------
__global__ __launch_bounds__(256) void ln_kernel(
    const float* __restrict__ x, const float* __restrict__ g,
    const float* __restrict__ b, float* __restrict__ y)
{
    const int row = blockIdx.x;
    const float* xr = x + (size_t)row * DIM;
    float v[2];
    float s = 0.f, s2 = 0.f;
#pragma unroll
    for (int it = 0; it < 2; it++) {
        v[it] = xr[threadIdx.x + it * 256];
        s += v[it]; s2 += v[it] * v[it];
    }
#pragma unroll
    for (int off = 16; off; off >>= 1) {
        s  += __shfl_xor_sync(0xffffffffu, s,  off);
        s2 += __shfl_xor_sync(0xffffffffu, s2, off);
    }
    __shared__ float rs[8], rs2[8];
    __shared__ float smean, srstd;
    const int w = threadIdx.x >> 5;
    if ((threadIdx.x & 31) == 0) { rs[w] = s; rs2[w] = s2; }
    __syncthreads();
    if (threadIdx.x == 0) {
        float a = 0.f, a2 = 0.f;
        for (int i = 0; i < 8; i++) { a += rs[i]; a2 += rs2[i]; }
        float mean = a * (1.f / DIM);
        float var  = a2 * (1.f / DIM) - mean * mean;
        smean = mean;
        srstd = rsqrtf(var + 1e-5f);
    }
    __syncthreads();
    const float mean = smean, rstd = srstd;
#pragma unroll
    for (int it = 0; it < 2; it++) {
        int c = threadIdx.x + it * 256;
        y[(size_t)row * DIM + c] = (v[it] - mean) * rstd * g[c] + b[c];
    }
}

// ---------------- TF32 tensor-core flash attention ----------------
// grid = (17 q-tiles of 128, 8 heads, 4 batch), block 256 (8 warps).
// Each warp owns 16 full query rows -> warp-local online softmax.
// qkv: [b, i, 1536]; Q @ h*64, K @ 512+h*64, V @ 1024+h*64.
#define ATP 68   // Qs/Ps pitch -> a-frag bank = 4r+j (conflict-free)
#define KVP 72   // Kd/Vs pitch -> b-frag bank = 8j+r (conflict-free)
#define NKT 33   // ceil(2049/64)
#define ATT_SMEM ((2 * 128 * ATP + 2 * 64 * KVP) * 4)   // 106496 bytes

__global__ __launch_bounds__(256, 2) void attn_tf32(
    const float* __restrict__ qkv, const int* __restrict__ lens,
    float* __restrict__ o)
{
    extern __shared__ float sm[];
    float* Qs = sm;                    // [128][ATP]
    float* Ps = Qs + 128 * ATP;        // [128][ATP]
    float* Kd = Ps + 128 * ATP;        // [64 d][KVP keys]  (= K^T)
    float* Vs = Kd + 64 * KVP;         // [64 keys][KVP d]

    const int tid  = threadIdx.x;
    const int lane = tid & 31;
    const int warp = tid >> 5;
    const int wq   = warp * 16;
    const int r    = lane >> 2;
    const int j    = lane & 3;

    const int qt = blockIdx.x, h = blockIdx.y, b = blockIdx.z;
    const int qbase = qt * 128;
    const int len1  = lens[b] + 1;
    const float* qkv_b = qkv + (size_t)b * N1 * H3;

    // ---- stage Q tile ----
#pragma unroll
    for (int i = 0; i < 8; i++) {
        int q  = i * 16 + (tid >> 4);
        int d0 = (tid & 15) * 4;
        int qg = qbase + q;
        float4 v = (qg < N1)
            ? *(const float4*)(qkv_b + (size_t)qg * H3 + h * 64 + d0)
            : make_float4(0.f, 0.f, 0.f, 0.f);
        *(float4*)&Qs[q * ATP + d0] = v;
    }

    const int row0g = qbase + wq + r;
    const int row1g = row0g + 8;
    const bool q0pad = row0g >= len1;
    const bool q1pad = row1g >= len1;

    float oacc[8][4];
#pragma unroll
    for (int nt = 0; nt < 8; nt++)
#pragma unroll
        for (int q = 0; q < 4; q++) oacc[nt][q] = 0.f;
    float m0 = -1e30f, m1 = -1e30f, l0 = 0.f, l1 = 0.f;

    for (int kt = 0; kt < NKT; kt++) {
        const int kbase = kt * 64;
        __syncthreads();   // prior PV reads done before K/V overwrite (also covers Qs staging)

        // ---- stage K (transposed) + V ----
#pragma unroll
        for (int i = 0; i < 4; i++) {
            int key = i * 16 + (tid >> 4);
            int d0  = (tid & 15) * 4;
            int kg  = kbase + key;
            float4 k4, v4;
            if (kg < N1) {
                const float* base = qkv_b + (size_t)kg * H3 + h * 64 + d0;
                k4 = *(const float4*)(base + 512);
                v4 = *(const float4*)(base + 1024);
            } else {
                k4 = v4 = make_float4(0.f, 0.f, 0.f, 0.f);
            }
            Kd[(d0 + 0) * KVP + key] = k4.x;
            Kd[(d0 + 1) * KVP + key] = k4.y;
            Kd[(d0 + 2) * KVP + key] = k4.z;
            Kd[(d0 + 3) * KVP + key] = k4.w;
            *(float4*)&Vs[key * KVP + d0] = v4;
        }
        __syncthreads();

        // ---- S = Q K^T ----
        float sacc[8][4];
#pragma unroll
        for (int nt = 0; nt < 8; nt++)
#pragma unroll
            for (int q = 0; q < 4; q++) sacc[nt][q] = 0.f;
#pragma unroll
        for (int kk = 0; kk < 64; kk += 8) {
            uint32_t af[4];
            af[0] = f2tf(Qs[(wq + r    ) * ATP + kk + j    ]);
            af[1] = f2tf(Qs[(wq + r + 8) * ATP + kk + j    ]);
            af[2] = f2tf(Qs[(wq + r    ) * ATP + kk + j + 4]);
            af[3] = f2tf(Qs[(wq + r + 8) * ATP + kk + j + 4]);
#pragma unroll
            for (int nt = 0; nt < 8; nt++) {
                uint32_t b0 = f2tf(Kd[(kk + j    ) * KVP + nt * 8 + r]);
                uint32_t b1 = f2tf(Kd[(kk + j + 4) * KVP + nt * 8 + r]);
                mma8(sacc[nt], af, b0, b1);
            }
        }

        // ---- scale + mask ----
#pragma unroll
        for (int nt = 0; nt < 8; nt++) {
#pragma unroll
            for (int cc = 0; cc < 2; cc++) {
                int kg = kbase + nt * 8 + 2 * j + cc;
                bool kinv = (kg >= N1);
                bool kpad = (kg >= len1);
                sacc[nt][cc]     = (kinv || (q0pad && kpad)) ? -1e30f : sacc[nt][cc]     * ATT_SCALE;
                sacc[nt][2 + cc] = (kinv || (q1pad && kpad)) ? -1e30f : sacc[nt][2 + cc] * ATT_SCALE;
            }
        }

        // ---- online softmax (warp-local, 4-lane row groups) ----
        float mx0 = -1e30f, mx1 = -1e30f;
#pragma unroll
        for (int nt = 0; nt < 8; nt++) {
            mx0 = fmaxf(mx0, fmaxf(sacc[nt][0], sacc[nt][1]));
            mx1 = fmaxf(mx1, fmaxf(sacc[nt][2], sacc[nt][3]));
        }
        mx0 = fmaxf(mx0, __shfl_xor_sync(0xffffffffu, mx0, 1));
        mx0 = fmaxf(mx0, __shfl_xor_sync(0xffffffffu, mx0, 2));
        mx1 = fmaxf(mx1, __shfl_xor_sync(0xffffffffu, mx1, 1));
        mx1 = fmaxf(mx1, __shfl_xor_sync(0xffffffffu, mx1, 2));
        float mn0 = fmaxf(m0, mx0), mn1 = fmaxf(m1, mx1);
        float f0 = __expf(m0 - mn0), f1 = __expf(m1 - mn1);
        m0 = mn0; m1 = mn1;
        float s0 = 0.f, s1 = 0.f;
#pragma unroll
        for (int nt = 0; nt < 8; nt++) {
#pragma unroll
            for (int cc = 0; cc < 2; cc++) {
                float p0 = __expf(sacc[nt][cc]     - m0);
                float p1 = __expf(sacc[nt][2 + cc] - m1);
                sacc[nt][cc] = p0;  sacc[nt][2 + cc] = p1;
                s0 += p0; s1 += p1;
            }
        }
        s0 += __shfl_xor_sync(0xffffffffu, s0, 1);
        s0 += __shfl_xor_sync(0xffffffffu, s0, 2);
        s1 += __shfl_xor_sync(0xffffffffu, s1, 1);
        s1 += __shfl_xor_sync(0xffffffffu, s1, 2);
        l0 = l0 * f0 + s0;
        l1 = l1 * f1 + s1;
#pragma unroll
        for (int nt = 0; nt < 8; nt++) {
            oacc[nt][0] *= f0; oacc[nt][1] *= f0;
            oacc[nt][2] *= f1; oacc[nt][3] *= f1;
        }

        // ---- P -> smem (c-layout), then PV via mma ----
#pragma unroll
        for (int nt = 0; nt < 8; nt++) {
            *(float2*)&Ps[(wq + r    ) * ATP + nt * 8 + 2 * j] = make_float2(sacc[nt][0], sacc[nt][1]);
            *(float2*)&Ps[(wq + r + 8) * ATP + nt * 8 + 2 * j] = make_float2(sacc[nt][2], sacc[nt][3]);
        }
        __syncwarp();

#pragma unroll
        for (int kk = 0; kk < 64; kk += 8) {
            uint32_t af[4];
            af[0] = f2tf(Ps[(wq + r    ) * ATP + kk + j    ]);
            af[1] = f2tf(Ps[(wq + r + 8) * ATP + kk + j    ]);
            af[2] = f2tf(Ps[(wq + r    ) * ATP + kk + j + 4]);
            af[3] = f2tf(Ps[(wq + r + 8) * ATP + kk + j + 4]);
#pragma unroll
            for (int nt = 0; nt < 8; nt++) {
                uint32_t b0 = f2tf(Vs[(kk + j    ) * KVP + nt * 8 + r]);
                uint32_t b1 = f2tf(Vs[(kk + j + 4) * KVP + nt * 8 + r]);
                mma8(oacc[nt], af, b0, b1);
            }
        }
    }

    // ---- normalize + write O ----
    float inv0 = 1.f / l0, inv1 = 1.f / l1;
    float* ob = o + (size_t)b * N1 * DIM + h * 64;
    if (row0g < N1) {
#pragma unroll
        for (int nt = 0; nt < 8; nt++)
            *(float2*)&ob[(size_t)row0g * DIM + nt * 8 + 2 * j] =
                make_float2(oacc[nt][0] * inv0, oacc[nt][1] * inv0);
    }
    if (row1g < N1) {
#pragma unroll
        for (int nt = 0; nt < 8; nt++)
            *(float2*)&ob[(size_t)row1g * DIM + nt * 8 + 2 * j] =
                make_float2(oacc[nt][2] * inv1, oacc[nt][3] * inv1);
    }
}

// ---------------- final LN + classifier head (cls token only) ----------------
__global__ __launch_bounds__(256) void head_kernel(
    const float* __restrict__ x, const float* __restrict__ g,
    const float* __restrict__ bb, const float* __restrict__ hw,
    const float* __restrict__ hb, float* __restrict__ out)
{
    const int b = blockIdx.x;
    const float* xr = x + (size_t)b * N1 * DIM;
    float v[2];
    float s = 0.f, s2 = 0.f;
#pragma unroll
    for (int it = 0; it < 2; it++) {
        v[it] = xr[threadIdx.x + it * 256];
        s += v[it]; s2 += v[it] * v[it];
    }
#pragma unroll
    for (int off = 16; off; off >>= 1) {
        s  += __shfl_xor_sync(0xffffffffu, s,  off);
        s2 += __shfl_xor_sync(0xffffffffu, s2, off);
    }
    __shared__ float rs[8], rs2[8];
    __shared__ float smean, srstd;
    const int w = threadIdx.x >> 5;
    if ((threadIdx.x & 31) == 0) { rs[w] = s; rs2[w] = s2; }
    __syncthreads();
    if (threadIdx.x == 0) {
        float a = 0.f, a2 = 0.f;
        for (int i = 0; i < 8; i++) { a += rs[i]; a2 += rs2[i]; }
        float mean = a * (1.f / DIM);
        float var  = a2 * (1.f / DIM) - mean * mean;
        smean = mean;
        srstd = rsqrtf(var + 1e-5f);
    }
    __syncthreads();
    const float mean = smean, rstd = srstd;

    float d0 = 0.f, d1 = 0.f;
#pragma unroll
    for (int it = 0; it < 2; it++) {
        int c = threadIdx.x + it * 256;
        float xn = (v[it] - mean) * rstd * g[c] + bb[c];
        d0 += xn * hw[2 * c + 0];
        d1 += xn * hw[2 * c + 1];
    }
#pragma unroll
    for (int off = 16; off; off >>= 1) {
        d0 += __shfl_xor_sync(0xffffffffu, d0, off);
        d1 += __shfl_xor_sync(0xffffffffu, d1, off);
    }
    __syncthreads();
    if ((threadIdx.x & 31) == 0) { rs[w] = d0; rs2[w] = d1; }
    __syncthreads();
    if (threadIdx.x == 0) {
        float a0 = 0.f, a1 = 0.f;
        for (int i = 0; i < 8; i++) { a0 += rs[i]; a1 += rs2[i]; }
        out[b * 2 + 0] = a0 + hb[0];
        out[b * 2 + 1] = a1 + hb[1];
    }
}

// ---------------- launch ----------------
extern "C" void kernel_launch(void* const* d_in, const int* in_sizes, int n_in,
                              void* d_out, int out_size)
{
    const float* x      = (const float*)d_in[0];
    const int*   lens   = (const int*)  d_in[1];
    const float* cls    = (const float*)d_in[2];
    const float* fc_w   = (const float*)d_in[3];
    const float* fc_b   = (const float*)d_in[4];
    const float* ln1_g  = (const float*)d_in[5];
    const float* ln1_b  = (const float*)d_in[6];
    const float* qkv_w  = (const float*)d_in[7];
    const float* out_w  = (const float*)d_in[8];
    const float* out_b  = (const float*)d_in[9];
    const float* ln2_g  = (const float*)d_in[10];
    const float* ln2_b  = (const float*)d_in[11];
    const float* ff1_w  = (const float*)d_in[12];
    const float* ff1_b  = (const float*)d_in[13];
    const float* ff2_w  = (const float*)d_in[14];
    const float* ff2_b  = (const float*)d_in[15];
    const float* lnf_g  = (const float*)d_in[16];
    const float* lnf_b  = (const float*)d_in[17];
    const float* head_w = (const float*)d_in[18];
    const float* head_b = (const float*)d_in[19];
    float* out = (float*)d_out;

    float *gx, *gxn, *gqkv, *go, *gh;
    cudaGetSymbolAddress((void**)&gx,   g_x);
    cudaGetSymbolAddress((void**)&gxn,  g_xn);
    cudaGetSymbolAddress((void**)&gqkv, g_qkv);
    cudaGetSymbolAddress((void**)&go,   g_o);
    cudaGetSymbolAddress((void**)&gh,   g_h);

    cudaFuncSetAttribute(attn_tf32, cudaFuncAttributeMaxDynamicSharedMemorySize, ATT_SMEM);

    // cls rows
    cls_fill_kernel<<<BATCH, DIM>>>(cls, gx);

    // fc + GELU, remapped into cls-offset layout: M=8192, N=512, K=768
    sgemm_tf32<<<dim3(DIM / 64, (BATCH * NTOK + 127) / 128), 256>>>(
        x, fc_w, fc_b, nullptr, gx, BATCH * NTOK, DIM, DIN, /*mode=*/2, /*remap=*/1);

    const int gy = (ROWS_TOT + 127) / 128;   // 65
    for (int l = 0; l < DEPTH; l++) {
        ln_kernel<<<ROWS_TOT, 256>>>(gx, ln1_g + l * DIM, ln1_b + l * DIM, gxn);
        sgemm_tf32<<<dim3(H3 / 64, gy), 256>>>(
            gxn, qkv_w + (size_t)l * DIM * H3, nullptr, nullptr, gqkv,
            ROWS_TOT, H3, DIM, 0, 0);
        attn_tf32<<<dim3((N1 + 127) / 128, 8, BATCH), 256, ATT_SMEM>>>(gqkv, lens, go);
        sgemm_tf32<<<dim3(DIM / 64, gy), 256>>>(
            go, out_w + (size_t)l * DIM * DIM, out_b + l * DIM, gx, gx,
            ROWS_TOT, DIM, DIM, 3, 0);
        ln_kernel<<<ROWS_TOT, 256>>>(gx, ln2_g + l * DIM, ln2_b + l * DIM, gxn);
        sgemm_tf32<<<dim3(DIM / 64, gy), 256>>>(
            gxn, ff1_w + (size_t)l * DIM * DIM, ff1_b + l * DIM, nullptr, gh,
            ROWS_TOT, DIM, DIM, 2, 0);
        sgemm_tf32<<<dim3(DIM / 64, gy), 256>>>(
            gh, ff2_w + (size_t)l * DIM * DIM, ff2_b + l * DIM, gx, gx,
            ROWS_TOT, DIM, DIM, 3, 0);
    }

    head_kernel<<<BATCH, 256>>>(gx, lnf_g, lnf_b, head_w, head_b, out);
}

// round 11
// speedup vs baseline: 3.3240x; 1.0589x over previous
#include <cuda_runtime.h>
#include <math.h>
#include <stdint.h>

// ---------------- problem constants ----------------
#define BATCH 4
#define NTOK  2048
#define N1    2049          // tokens + cls
#define DIN   768
#define DIM   512
#define H3    1536          // 3*H*DH
#define DEPTH 2
#define ROWS_TOT (BATCH * N1)   // 8196
#define ATT_SCALE 0.125f        // 64^-0.5

// ---------------- scratch (device globals; allocation-free) ----------------
__device__ __align__(256) float g_x  [BATCH * N1 * DIM];
__device__ __align__(256) float g_xn [BATCH * N1 * DIM];
__device__ __align__(256) float g_qkv[BATCH * N1 * H3];
__device__ __align__(256) float g_o  [BATCH * N1 * DIM];
__device__ __align__(256) float g_h  [BATCH * N1 * DIM];

// ---------------- helpers ----------------
__device__ __forceinline__ float gelu_exact(float v) {
    return 0.5f * v * (1.0f + erff(v * 0.70710678118654752440f));
}

__device__ __forceinline__ uint32_t f2tf(float f) {
    uint32_t u;
    asm("cvt.rna.tf32.f32 %0, %1;" : "=r"(u) : "f"(f));
    return u;
}
__device__ __forceinline__ uint4 f4tf(float4 v) {
    return make_uint4(f2tf(v.x), f2tf(v.y), f2tf(v.z), f2tf(v.w));
}

// D += A(16x8,row) * B(8x8,col)  tf32, fp32 accum
__device__ __forceinline__ void mma8(float* c, const uint32_t* a, uint32_t b0, uint32_t b1) {
    asm volatile(
        "mma.sync.aligned.m16n8k8.row.col.f32.tf32.tf32.f32 "
        "{%0,%1,%2,%3}, {%4,%5,%6,%7}, {%8,%9}, {%0,%1,%2,%3};"
        : "+f"(c[0]), "+f"(c[1]), "+f"(c[2]), "+f"(c[3])
        : "r"(a[0]), "r"(a[1]), "r"(a[2]), "r"(a[3]), "r"(b0), "r"(b1));
}

// ---------------- cls token fill ----------------
__global__ void cls_fill_kernel(const float* __restrict__ cls, float* __restrict__ x) {
    x[(size_t)blockIdx.x * N1 * DIM + threadIdx.x] = cls[threadIdx.x];
}

// ---------------- TF32 tensor-core SGEMM with fused epilogue ----------------
// C[M,N] = A[M,K] @ B[K,N] (row-major). mode: 0 none, 1 +bias, 2 gelu(.+bias),
// 3 +bias+residual. remap: out row r -> r + r/2048 + 1 (cls insertion, fc only).
// Block 128x64x32, 8 warps as 4x2 of 32x32 warp tiles, m16n8k8 tf32 mma.
// Smem tiles hold PRE-CONVERTED tf32 bit patterns (cvt once at store).
#define BM 128
#define BN 64
#define BK 32
#define AP 36   // As pitch -> a-frag bank = 4r+j (conflict-free)
#define BP 72   // Bs pitch -> b-frag bank = 8j+r (conflict-free)

__global__ __launch_bounds__(256, 2) void sgemm_tf32(
    const float* __restrict__ A, const float* __restrict__ B,
    const float* __restrict__ bias, const float* __restrict__ res,
    float* __restrict__ C, int M, int N, int K, int mode, int remap)
{
    __shared__ uint32_t As[BM * AP];
    __shared__ uint32_t Bs[BK * BP];

    const int tid  = threadIdx.x;
    const int lane = tid & 31;
    const int warp = tid >> 5;
    const int wm   = (warp >> 1) * 32;
    const int wn   = (warp & 1) * 32;
    const int r    = lane >> 2;
    const int j    = lane & 3;
    const int row0 = blockIdx.y * BM;
    const int col0 = blockIdx.x * BN;

    const int a_r = tid >> 3;            // 0..31 (4 iters of +32)
    const int a_k = (tid & 7) * 4;       // 0..28
    const int b_k = tid >> 4;            // 0..15 (2 iters of +16)
    const int b_n = (tid & 15) * 4;      // 0..60

    float acc[2][4][4];
#pragma unroll
    for (int mt = 0; mt < 2; mt++)
#pragma unroll
        for (int nt = 0; nt < 4; nt++)
#pragma unroll
            for (int q = 0; q < 4; q++) acc[mt][nt][q] = 0.f;

    float4 pa[4], pb[2];
#pragma unroll
    for (int i = 0; i < 4; i++) {
        int grow = row0 + i * 32 + a_r;
        pa[i] = (grow < M) ? *(const float4*)(A + (size_t)grow * K + a_k)
                           : make_float4(0.f, 0.f, 0.f, 0.f);
    }
#pragma unroll
    for (int i = 0; i < 2; i++)
        pb[i] = *(const float4*)(B + (size_t)(i * 16 + b_k) * N + col0 + b_n);

    const int KB = K / BK;
    for (int kb = 0; kb < KB; kb++) {
#pragma unroll
        for (int i = 0; i < 4; i++)
            *(uint4*)&As[(i * 32 + a_r) * AP + a_k] = f4tf(pa[i]);
#pragma unroll
        for (int i = 0; i < 2; i++)
            *(uint4*)&Bs[(i * 16 + b_k) * BP + b_n] = f4tf(pb[i]);
        __syncthreads();

        if (kb + 1 < KB) {
            const int k0 = (kb + 1) * BK;
#pragma unroll
            for (int i = 0; i < 4; i++) {
                int grow = row0 + i * 32 + a_r;
                pa[i] = (grow < M) ? *(const float4*)(A + (size_t)grow * K + k0 + a_k)
                                   : make_float4(0.f, 0.f, 0.f, 0.f);
            }
#pragma unroll
            for (int i = 0; i < 2; i++)
                pb[i] = *(const float4*)(B + (size_t)(k0 + i * 16 + b_k) * N + col0 + b_n);
        }

#pragma unroll
        for (int kk = 0; kk < BK; kk += 8) {
            uint32_t af[2][4];
#pragma unroll
            for (int mt = 0; mt < 2; mt++) {
                int mb = wm + mt * 16;
                af[mt][0] = As[(mb + r    ) * AP + kk + j    ];
                af[mt][1] = As[(mb + r + 8) * AP + kk + j    ];
                af[mt][2] = As[(mb + r    ) * AP + kk + j + 4];
                af[mt][3] = As[(mb + r + 8) * AP + kk + j + 4];
            }
#pragma unroll
            for (int nt = 0; nt < 4; nt++) {
                uint32_t b0 = Bs[(kk + j    ) * BP + wn + nt * 8 + r];
                uint32_t b1 = Bs[(kk + j + 4) * BP + wn + nt * 8 + r];
                mma8(acc[0][nt], af[0], b0, b1);
                mma8(acc[1][nt], af[1], b0, b1);
            }
        }
        __syncthreads();
    }

#pragma unroll
    for (int mt = 0; mt < 2; mt++) {
#pragma unroll
        for (int half = 0; half < 2; half++) {
            int grow = row0 + wm + mt * 16 + r + half * 8;
            if (grow >= M) continue;
            size_t orow = remap ? (size_t)(grow + grow / 2048 + 1) : (size_t)grow;
#pragma unroll
            for (int nt = 0; nt < 4; nt++) {
                int gc = col0 + wn + nt * 8 + 2 * j;
                float v0 = acc[mt][nt][half * 2 + 0];
                float v1 = acc[mt][nt][half * 2 + 1];
                if (mode >= 1) { v0 += bias[gc]; v1 += bias[gc + 1]; }
                if (mode == 2) { v0 = gelu_exact(v0); v1 = gelu_exact(v1); }
                float* cp = C + orow * N + gc;
                if (mode == 3) {
                    const float* rp = res + orow * N + gc;
                    v0 += rp[0]; v1 += rp[1];
                }
                *(float2*)cp = make_float2(v0, v1);
            }
        }
    }
}

// ---------------- LayerNorm (one block per row, D=512) ----------------
__global__ __launch_bounds__(256) void ln_kernel(
    const float* __restrict__ x, const float* __restrict__ g,
    const float* __restrict__ b, float* __restrict__ y)
{
    const int row = blockIdx.x;
    const float* xr = x + (size_t)row * DIM;
    float v[2];
    float s = 0.f, s2 = 0.f;
#pragma unroll
    for (int it = 0; it < 2; it++) {
        v[it] = xr[threadIdx.x + it * 256];
        s += v[it]; s2 += v[it] * v[it];
    }
#pragma unroll
    for (int off = 16; off; off >>= 1) {
        s  += __shfl_xor_sync(0xffffffffu, s,  off);
        s2 += __shfl_xor_sync(0xffffffffu, s2, off);
    }
    __shared__ float rs[8], rs2[8];
    __shared__ float smean, srstd;
    const int w = threadIdx.x >> 5;
    if ((threadIdx.x & 31) == 0) { rs[w] = s; rs2[w] = s2; }
    __syncthreads();
    if (threadIdx.x == 0) {
        float a = 0.f, a2 = 0.f;
        for (int i = 0; i < 8; i++) { a += rs[i]; a2 += rs2[i]; }
        float mean = a * (1.f / DIM);
        float var  = a2 * (1.f / DIM) - mean * mean;
        smean = mean;
        srstd = rsqrtf(var + 1e-5f);
    }
    __syncthreads();
    const float mean = smean, rstd = srstd;
#pragma unroll
    for (int it = 0; it < 2; it++) {
        int c = threadIdx.x + it * 256;
        y[(size_t)row * DIM + c] = (v[it] - mean) * rstd * g[c] + b[c];
    }
}

// ---------------- TF32 tensor-core flash attention ----------------
// grid = (17 q-tiles of 128, 8 heads, 4 batch), block 256 (8 warps).
// Each warp owns 16 full query rows -> warp-local online softmax.
// Smem tiles hold pre-converted tf32 bits; accumulators fp32.
#define ATP 68   // Qs/Ps pitch -> a-frag bank = 4r+j (conflict-free)
#define KVP 72   // Kd/Vs pitch -> b-frag bank = 8j+r (conflict-free)
#define NKT 33   // ceil(2049/64)
#define ATT_SMEM ((2 * 128 * ATP + 2 * 64 * KVP) * 4)   // 106496 bytes

__global__ __launch_bounds__(256, 2) void attn_tf32(
    const float* __restrict__ qkv, const int* __restrict__ lens,
    float* __restrict__ o)
{
    extern __shared__ uint32_t sm[];
    uint32_t* Qs = sm;                    // [128][ATP]
    uint32_t* Ps = Qs + 128 * ATP;        // [128][ATP]
    uint32_t* Kd = Ps + 128 * ATP;        // [64 d][KVP keys]  (= K^T)
    uint32_t* Vs = Kd + 64 * KVP;         // [64 keys][KVP d]

    const int tid  = threadIdx.x;
    const int lane = tid & 31;
    const int warp = tid >> 5;
    const int wq   = warp * 16;
    const int r    = lane >> 2;
    const int j    = lane & 3;

    const int qt = blockIdx.x, h = blockIdx.y, b = blockIdx.z;
    const int qbase = qt * 128;
    const int len1  = lens[b] + 1;
    const float* qkv_b = qkv + (size_t)b * N1 * H3;

    // ---- stage Q tile (tf32) ----
#pragma unroll
    for (int i = 0; i < 8; i++) {
        int q  = i * 16 + (tid >> 4);
        int d0 = (tid & 15) * 4;
        int qg = qbase + q;
        float4 v = (qg < N1)
            ? *(const float4*)(qkv_b + (size_t)qg * H3 + h * 64 + d0)
            : make_float4(0.f, 0.f, 0.f, 0.f);
        *(uint4*)&Qs[q * ATP + d0] = f4tf(v);
    }

    const int row0g = qbase + wq + r;
    const int row1g = row0g + 8;
    const bool q0pad = row0g >= len1;
    const bool q1pad = row1g >= len1;

    float oacc[8][4];
#pragma unroll
    for (int nt = 0; nt < 8; nt++)
#pragma unroll
        for (int q = 0; q < 4; q++) oacc[nt][q] = 0.f;
    float m0 = -1e30f, m1 = -1e30f, l0 = 0.f, l1 = 0.f;

    for (int kt = 0; kt < NKT; kt++) {
        const int kbase = kt * 64;
        __syncthreads();   // prior PV reads done before K/V overwrite (covers Qs staging too)

        // ---- stage K (transposed) + V, tf32 ----
#pragma unroll
        for (int i = 0; i < 4; i++) {
            int key = i * 16 + (tid >> 4);
            int d0  = (tid & 15) * 4;
            int kg  = kbase + key;
            float4 k4, v4;
            if (kg < N1) {
                const float* base = qkv_b + (size_t)kg * H3 + h * 64 + d0;
                k4 = *(const float4*)(base + 512);
                v4 = *(const float4*)(base + 1024);
            } else {
                k4 = v4 = make_float4(0.f, 0.f, 0.f, 0.f);
            }
            Kd[(d0 + 0) * KVP + key] = f2tf(k4.x);
            Kd[(d0 + 1) * KVP + key] = f2tf(k4.y);
            Kd[(d0 + 2) * KVP + key] = f2tf(k4.z);
            Kd[(d0 + 3) * KVP + key] = f2tf(k4.w);
            *(uint4*)&Vs[key * KVP + d0] = f4tf(v4);
        }
        __syncthreads();

        // ---- S = Q K^T ----
        float sacc[8][4];
#pragma unroll
        for (int nt = 0; nt < 8; nt++)
#pragma unroll
            for (int q = 0; q < 4; q++) sacc[nt][q] = 0.f;
#pragma unroll
        for (int kk = 0; kk < 64; kk += 8) {
            uint32_t af[4];
            af[0] = Qs[(wq + r    ) * ATP + kk + j    ];
            af[1] = Qs[(wq + r + 8) * ATP + kk + j    ];
            af[2] = Qs[(wq + r    ) * ATP + kk + j + 4];
            af[3] = Qs[(wq + r + 8) * ATP + kk + j + 4];
#pragma unroll
            for (int nt = 0; nt < 8; nt++) {
                uint32_t b0 = Kd[(kk + j    ) * KVP + nt * 8 + r];
                uint32_t b1 = Kd[(kk + j + 4) * KVP + nt * 8 + r];
                mma8(sacc[nt], af, b0, b1);
            }
        }

        // ---- scale + mask ----
#pragma unroll
        for (int nt = 0; nt < 8; nt++) {
#pragma unroll
            for (int cc = 0; cc < 2; cc++) {
                int kg = kbase + nt * 8 + 2 * j + cc;
                bool kinv = (kg >= N1);
                bool kpad = (kg >= len1);
                sacc[nt][cc]     = (kinv || (q0pad && kpad)) ? -1e30f : sacc[nt][cc]     * ATT_SCALE;
                sacc[nt][2 + cc] = (kinv || (q1pad && kpad)) ? -1e30f : sacc[nt][2 + cc] * ATT_SCALE;
            }
        }

        // ---- online softmax (warp-local, 4-lane row groups) ----
        float mx0 = -1e30f, mx1 = -1e30f;
#pragma unroll
        for (int nt = 0; nt < 8; nt++) {
            mx0 = fmaxf(mx0, fmaxf(sacc[nt][0], sacc[nt][1]));
            mx1 = fmaxf(mx1, fmaxf(sacc[nt][2], sacc[nt][3]));
        }
        mx0 = fmaxf(mx0, __shfl_xor_sync(0xffffffffu, mx0, 1));
        mx0 = fmaxf(mx0, __shfl_xor_sync(0xffffffffu, mx0, 2));
        mx1 = fmaxf(mx1, __shfl_xor_sync(0xffffffffu, mx1, 1));
        mx1 = fmaxf(mx1, __shfl_xor_sync(0xffffffffu, mx1, 2));
        float mn0 = fmaxf(m0, mx0), mn1 = fmaxf(m1, mx1);
        float f0 = __expf(m0 - mn0), f1 = __expf(m1 - mn1);
        m0 = mn0; m1 = mn1;
        float s0 = 0.f, s1 = 0.f;
#pragma unroll
        for (int nt = 0; nt < 8; nt++) {
#pragma unroll
            for (int cc = 0; cc < 2; cc++) {
                float p0 = __expf(sacc[nt][cc]     - m0);
                float p1 = __expf(sacc[nt][2 + cc] - m1);
                sacc[nt][cc] = p0;  sacc[nt][2 + cc] = p1;
                s0 += p0; s1 += p1;
            }
        }
        s0 += __shfl_xor_sync(0xffffffffu, s0, 1);
        s0 += __shfl_xor_sync(0xffffffffu, s0, 2);
        s1 += __shfl_xor_sync(0xffffffffu, s1, 1);
        s1 += __shfl_xor_sync(0xffffffffu, s1, 2);
        l0 = l0 * f0 + s0;
        l1 = l1 * f1 + s1;
#pragma unroll
        for (int nt = 0; nt < 8; nt++) {
            oacc[nt][0] *= f0; oacc[nt][1] *= f0;
            oacc[nt][2] *= f1; oacc[nt][3] *= f1;
        }

        // ---- P -> smem as tf32 (c-layout), then PV via mma ----
#pragma unroll
        for (int nt = 0; nt < 8; nt++) {
            *(uint2*)&Ps[(wq + r    ) * ATP + nt * 8 + 2 * j] =
                make_uint2(f2tf(sacc[nt][0]), f2tf(sacc[nt][1]));
            *(uint2*)&Ps[(wq + r + 8) * ATP + nt * 8 + 2 * j] =
                make_uint2(f2tf(sacc[nt][2]), f2tf(sacc[nt][3]));
        }
        __syncwarp();

#pragma unroll
        for (int kk = 0; kk < 64; kk += 8) {
            uint32_t af[4];
            af[0] = Ps[(wq + r    ) * ATP + kk + j    ];
            af[1] = Ps[(wq + r + 8) * ATP + kk + j    ];
            af[2] = Ps[(wq + r    ) * ATP + kk + j + 4];
            af[3] = Ps[(wq + r + 8) * ATP + kk + j + 4];
#pragma unroll
            for (int nt = 0; nt < 8; nt++) {
                uint32_t b0 = Vs[(kk + j    ) * KVP + nt * 8 + r];
                uint32_t b1 = Vs[(kk + j + 4) * KVP + nt * 8 + r];
                mma8(oacc[nt], af, b0, b1);
            }
        }
    }

    // ---- normalize + write O ----
    float inv0 = 1.f / l0, inv1 = 1.f / l1;
    float* ob = o + (size_t)b * N1 * DIM + h * 64;
    if (row0g < N1) {
#pragma unroll
        for (int nt = 0; nt < 8; nt++)
            *(float2*)&ob[(size_t)row0g * DIM + nt * 8 + 2 * j] =
                make_float2(oacc[nt][0] * inv0, oacc[nt][1] * inv0);
    }
    if (row1g < N1) {
#pragma unroll
        for (int nt = 0; nt < 8; nt++)
            *(float2*)&ob[(size_t)row1g * DIM + nt * 8 + 2 * j] =
                make_float2(oacc[nt][2] * inv1, oacc[nt][3] * inv1);
    }
}

// ---------------- final LN + classifier head (cls token only) ----------------
__global__ __launch_bounds__(256) void head_kernel(
    const float* __restrict__ x, const float* __restrict__ g,
    const float* __restrict__ bb, const float* __restrict__ hw,
    const float* __restrict__ hb, float* __restrict__ out)
{
    const int b = blockIdx.x;
    const float* xr = x + (size_t)b * N1 * DIM;
    float v[2];
    float s = 0.f, s2 = 0.f;
#pragma unroll
    for (int it = 0; it < 2; it++) {
        v[it] = xr[threadIdx.x + it * 256];
        s += v[it]; s2 += v[it] * v[it];
    }
#pragma unroll
    for (int off = 16; off; off >>= 1) {
        s  += __shfl_xor_sync(0xffffffffu, s,  off);
        s2 += __shfl_xor_sync(0xffffffffu, s2, off);
    }
    __shared__ float rs[8], rs2[8];
    __shared__ float smean, srstd;
    const int w = threadIdx.x >> 5;
    if ((threadIdx.x & 31) == 0) { rs[w] = s; rs2[w] = s2; }
    __syncthreads();
    if (threadIdx.x == 0) {
        float a = 0.f, a2 = 0.f;
        for (int i = 0; i < 8; i++) { a += rs[i]; a2 += rs2[i]; }
        float mean = a * (1.f / DIM);
        float var  = a2 * (1.f / DIM) - mean * mean;
        smean = mean;
        srstd = rsqrtf(var + 1e-5f);
    }
    __syncthreads();
    const float mean = smean, rstd = srstd;

    float d0 = 0.f, d1 = 0.f;
#pragma unroll
    for (int it = 0; it < 2; it++) {
        int c = threadIdx.x + it * 256;
        float xn = (v[it] - mean) * rstd * g[c] + bb[c];
        d0 += xn * hw[2 * c + 0];
        d1 += xn * hw[2 * c + 1];
    }
#pragma unroll
    for (int off = 16; off; off >>= 1) {
        d0 += __shfl_xor_sync(0xffffffffu, d0, off);
        d1 += __shfl_xor_sync(0xffffffffu, d1, off);
    }
    __syncthreads();
    if ((threadIdx.x & 31) == 0) { rs[w] = d0; rs2[w] = d1; }
    __syncthreads();
    if (threadIdx.x == 0) {
        float a0 = 0.f, a1 = 0.f;
        for (int i = 0; i < 8; i++) { a0 += rs[i]; a1 += rs2[i]; }
        out[b * 2 + 0] = a0 + hb[0];
        out[b * 2 + 1] = a1 + hb[1];
    }
}

// ---------------- launch ----------------
extern "C" void kernel_launch(void* const* d_in, const int* in_sizes, int n_in,
                              void* d_out, int out_size)
{
    const float* x      = (const float*)d_in[0];
    const int*   lens   = (const int*)  d_in[1];
    const float* cls    = (const float*)d_in[2];
    const float* fc_w   = (const float*)d_in[3];
    const float* fc_b   = (const float*)d_in[4];
    const float* ln1_g  = (const float*)d_in[5];
    const float* ln1_b  = (const float*)d_in[6];
    const float* qkv_w  = (const float*)d_in[7];
    const float* out_w  = (const float*)d_in[8];
    const float* out_b  = (const float*)d_in[9];
    const float* ln2_g  = (const float*)d_in[10];
    const float* ln2_b  = (const float*)d_in[11];
    const float* ff1_w  = (const float*)d_in[12];
    const float* ff1_b  = (const float*)d_in[13];
    const float* ff2_w  = (const float*)d_in[14];
    const float* ff2_b  = (const float*)d_in[15];
    const float* lnf_g  = (const float*)d_in[16];
    const float* lnf_b  = (const float*)d_in[17];
    const float* head_w = (const float*)d_in[18];
    const float* head_b = (const float*)d_in[19];
    float* out = (float*)d_out;

    float *gx, *gxn, *gqkv, *go, *gh;
    cudaGetSymbolAddress((void**)&gx,   g_x);
    cudaGetSymbolAddress((void**)&gxn,  g_xn);
    cudaGetSymbolAddress((void**)&gqkv, g_qkv);
    cudaGetSymbolAddress((void**)&go,   g_o);
    cudaGetSymbolAddress((void**)&gh,   g_h);

    cudaFuncSetAttribute(attn_tf32, cudaFuncAttributeMaxDynamicSharedMemorySize, ATT_SMEM);

    // cls rows
    cls_fill_kernel<<<BATCH, DIM>>>(cls, gx);

    // fc + GELU, remapped into cls-offset layout: M=8192, N=512, K=768
    sgemm_tf32<<<dim3(DIM / 64, (BATCH * NTOK + 127) / 128), 256>>>(
        x, fc_w, fc_b, nullptr, gx, BATCH * NTOK, DIM, DIN, /*mode=*/2, /*remap=*/1);

    const int gy = (ROWS_TOT + 127) / 128;   // 65
    for (int l = 0; l < DEPTH; l++) {
        ln_kernel<<<ROWS_TOT, 256>>>(gx, ln1_g + l * DIM, ln1_b + l * DIM, gxn);
        sgemm_tf32<<<dim3(H3 / 64, gy), 256>>>(
            gxn, qkv_w + (size_t)l * DIM * H3, nullptr, nullptr, gqkv,
            ROWS_TOT, H3, DIM, 0, 0);
        attn_tf32<<<dim3((N1 + 127) / 128, 8, BATCH), 256, ATT_SMEM>>>(gqkv, lens, go);
        sgemm_tf32<<<dim3(DIM / 64, gy), 256>>>(
            go, out_w + (size_t)l * DIM * DIM, out_b + l * DIM, gx, gx,
            ROWS_TOT, DIM, DIM, 3, 0);
        ln_kernel<<<ROWS_TOT, 256>>>(gx, ln2_g + l * DIM, ln2_b + l * DIM, gxn);
        sgemm_tf32<<<dim3(DIM / 64, gy), 256>>>(
            gxn, ff1_w + (size_t)l * DIM * DIM, ff1_b + l * DIM, nullptr, gh,
            ROWS_TOT, DIM, DIM, 2, 0);
        sgemm_tf32<<<dim3(DIM / 64, gy), 256>>>(
            gh, ff2_w + (size_t)l * DIM * DIM, ff2_b + l * DIM, gx, gx,
            ROWS_TOT, DIM, DIM, 3, 0);
    }

    head_kernel<<<BATCH, 256>>>(gx, lnf_g, lnf_b, head_w, head_b, out);
}

// round 12
// speedup vs baseline: 4.7547x; 1.4304x over previous
#include <cuda_runtime.h>
#include <math.h>
#include <stdint.h>

// ---------------- problem constants ----------------
#define BATCH 4
#define NTOK  2048
#define N1    2049          // tokens + cls
#define DIN   768
#define DIM   512
#define H3    1536          // 3*H*DH
#define DEPTH 2
#define ROWS_TOT (BATCH * N1)   // 8196
#define ATT_SCALE 0.125f        // 64^-0.5

// ---------------- scratch (device globals; allocation-free) ----------------
__device__ __align__(256) float g_x  [BATCH * N1 * DIM];
__device__ __align__(256) float g_xn [BATCH * N1 * DIM];
__device__ __align__(256) float g_qkv[BATCH * N1 * H3];
__device__ __align__(256) float g_o  [BATCH * N1 * DIM];
__device__ __align__(256) float g_h  [BATCH * N1 * DIM];

// ---------------- helpers ----------------
__device__ __forceinline__ float gelu_exact(float v) {
    return 0.5f * v * (1.0f + erff(v * 0.70710678118654752440f));
}

// D += A(16x8,row) * B(8x8,col)  tf32 (raw fp32 bits; HW truncates), fp32 accum
__device__ __forceinline__ void mma8(float* c, const uint32_t* a, uint32_t b0, uint32_t b1) {
    asm volatile(
        "mma.sync.aligned.m16n8k8.row.col.f32.tf32.tf32.f32 "
        "{%0,%1,%2,%3}, {%4,%5,%6,%7}, {%8,%9}, {%0,%1,%2,%3};"
        : "+f"(c[0]), "+f"(c[1]), "+f"(c[2]), "+f"(c[3])
        : "r"(a[0]), "r"(a[1]), "r"(a[2]), "r"(a[3]), "r"(b0), "r"(b1));
}

__device__ __forceinline__ uint32_t smem_u32(const void* p) {
    return (uint32_t)__cvta_generic_to_shared(p);
}
// 16B async copy, zero-fill when !pred (src not dereferenced when src-size==0)
__device__ __forceinline__ void cp16(uint32_t dst, const void* src, bool pred) {
    asm volatile("cp.async.cg.shared.global [%0], [%1], 16, %2;"
                 :: "r"(dst), "l"(src), "r"(pred ? 16 : 0));
}
__device__ __forceinline__ void cp_commit() { asm volatile("cp.async.commit_group;"); }
__device__ __forceinline__ void cp_wait0()  { asm volatile("cp.async.wait_group 0;"); }

// ---------------- cls token fill ----------------
__global__ void cls_fill_kernel(const float* __restrict__ cls, float* __restrict__ x) {
    x[(size_t)blockIdx.x * N1 * DIM + threadIdx.x] = cls[threadIdx.x];
}

// ---------------- TF32 tensor-core SGEMM, cp.async double-buffered ----------------
// C[M,N] = A[M,K] @ B[K,N]. mode: 0 none, 1 +bias, 2 gelu(.+bias), 3 +bias+res.
// remap: out row r -> r + r/2048 + 1. Block 128x64x32, 8 warps (4m x 2n) of 32x32.
#define BM 128
#define BN 64
#define BK 32
#define AP 36     // a-frag bank = 4r+j (conflict-free)
#define BP 72     // b-frag bank = 8j+r (conflict-free)
#define SBUF (BM * AP + BK * BP)                 // 6912 floats per buffer
#define GEMM_SMEM (2 * SBUF * 4)                 // 55296 bytes

__global__ __launch_bounds__(256, 3) void sgemm_tf32(
    const float* __restrict__ A, const float* __restrict__ B,
    const float* __restrict__ bias, const float* __restrict__ res,
    float* __restrict__ C, int M, int N, int K, int mode, int remap)
{
    extern __shared__ float gsm[];
    float* As0 = gsm;
    float* Bs0 = gsm + BM * AP;
    float* As1 = gsm + SBUF;
    float* Bs1 = As1 + BM * AP;

    const int tid  = threadIdx.x;
    const int lane = tid & 31;
    const int warp = tid >> 5;
    const int wm   = (warp >> 1) * 32;
    const int wn   = (warp & 1) * 32;
    const int r    = lane >> 2;
    const int j    = lane & 3;
    const int row0 = blockIdx.y * BM;
    const int col0 = blockIdx.x * BN;

    const int a_r = tid >> 3;            // 0..31 (x4 iters of +32)
    const int a_k = (tid & 7) * 4;       // 0..28
    const int b_k = tid >> 4;            // 0..15 (x2 iters of +16)
    const int b_n = (tid & 15) * 4;      // 0..60

    float acc[2][4][4];
#pragma unroll
    for (int mt = 0; mt < 2; mt++)
#pragma unroll
        for (int nt = 0; nt < 4; nt++)
#pragma unroll
            for (int q = 0; q < 4; q++) acc[mt][nt][q] = 0.f;

    // stage tile 0
    {
        float* Ad = As0; float* Bd = Bs0;
#pragma unroll
        for (int i = 0; i < 4; i++) {
            int grow = row0 + i * 32 + a_r;
            cp16(smem_u32(&Ad[(i * 32 + a_r) * AP + a_k]),
                 A + (size_t)(grow < M ? grow : 0) * K + a_k, grow < M);
        }
#pragma unroll
        for (int i = 0; i < 2; i++)
            cp16(smem_u32(&Bd[(i * 16 + b_k) * BP + b_n]),
                 B + (size_t)(i * 16 + b_k) * N + col0 + b_n, true);
        cp_commit();
    }

    const int KB = K / BK;
    for (int kb = 0; kb < KB; kb++) {
        cp_wait0();
        __syncthreads();

        const float* Asp = (kb & 1) ? As1 : As0;
        const float* Bsp = (kb & 1) ? Bs1 : Bs0;

        if (kb + 1 < KB) {
            const int k0 = (kb + 1) * BK;
            float* Ad = (kb & 1) ? As0 : As1;
            float* Bd = (kb & 1) ? Bs0 : Bs1;
#pragma unroll
            for (int i = 0; i < 4; i++) {
                int grow = row0 + i * 32 + a_r;
                cp16(smem_u32(&Ad[(i * 32 + a_r) * AP + a_k]),
                     A + (size_t)(grow < M ? grow : 0) * K + k0 + a_k, grow < M);
            }
#pragma unroll
            for (int i = 0; i < 2; i++)
                cp16(smem_u32(&Bd[(i * 16 + b_k) * BP + b_n]),
                     B + (size_t)(k0 + i * 16 + b_k) * N + col0 + b_n, true);
            cp_commit();
        }

#pragma unroll
        for (int kk = 0; kk < BK; kk += 8) {
            uint32_t af[2][4];
#pragma unroll
            for (int mt = 0; mt < 2; mt++) {
                int mb = wm + mt * 16;
                af[mt][0] = __float_as_uint(Asp[(mb + r    ) * AP + kk + j    ]);
                af[mt][1] = __float_as_uint(Asp[(mb + r + 8) * AP + kk + j    ]);
                af[mt][2] = __float_as_uint(Asp[(mb + r    ) * AP + kk + j + 4]);
                af[mt][3] = __float_as_uint(Asp[(mb + r + 8) * AP + kk + j + 4]);
            }
#pragma unroll
            for (int nt = 0; nt < 4; nt++) {
                uint32_t b0 = __float_as_uint(Bsp[(kk + j    ) * BP + wn + nt * 8 + r]);
                uint32_t b1 = __float_as_uint(Bsp[(kk + j + 4) * BP + wn + nt * 8 + r]);
                mma8(acc[0][nt], af[0], b0, b1);
                mma8(acc[1][nt], af[1], b0, b1);
            }
        }
    }

#pragma unroll
    for (int mt = 0; mt < 2; mt++) {
#pragma unroll
        for (int half = 0; half < 2; half++) {
            int grow = row0 + wm + mt * 16 + r + half * 8;
            if (grow >= M) continue;
            size_t orow = remap ? (size_t)(grow + grow / 2048 + 1) : (size_t)grow;
#pragma unroll
            for (int nt = 0; nt < 4; nt++) {
                int gc = col0 + wn + nt * 8 + 2 * j;
                float v0 = acc[mt][nt][half * 2 + 0];
                float v1 = acc[mt][nt][half * 2 + 1];
                if (mode >= 1) { v0 += bias[gc]; v1 += bias[gc + 1]; }
                if (mode == 2) { v0 = gelu_exact(v0); v1 = gelu_exact(v1); }
                float* cp = C + orow * N + gc;
                if (mode == 3) {
                    const float* rp = res + orow * N + gc;
                    v0 += rp[0]; v1 += rp[1];
                }
                *(float2*)cp = make_float2(v0, v1);
            }
        }
    }
}

// ---------------- LayerNorm (one block per row, D=512) ----------------
__global__ __launch_bounds__(256) void ln_kernel(
    const float* __restrict__ x, const float* __restrict__ g,
    const float* __restrict__ b, float* __restrict__ y)
{
    const int row = blockIdx.x;
    const float* xr = x + (size_t)row * DIM;
    float v[2];
    float s = 0.f, s2 = 0.f;
#pragma unroll
    for (int it = 0; it < 2; it++) {
        v[it] = xr[threadIdx.x + it * 256];
        s += v[it]; s2 += v[it] * v[it];
    }
#pragma unroll
    for (int off = 16; off; off >>= 1) {
        s  += __shfl_xor_sync(0xffffffffu, s,  off);
        s2 += __shfl_xor_sync(0xffffffffu, s2, off);
    }
    __shared__ float rs[8], rs2[8];
    __shared__ float smean, srstd;
    const int w = threadIdx.x >> 5;
    if ((threadIdx.x & 31) == 0) { rs[w] = s; rs2[w] = s2; }
    __syncthreads();
    if (threadIdx.x == 0) {
        float a = 0.f, a2 = 0.f;
        for (int i = 0; i < 8; i++) { a += rs[i]; a2 += rs2[i]; }
        float mean = a * (1.f / DIM);
        float var  = a2 * (1.f / DIM) - mean * mean;
        smean = mean;
        srstd = rsqrtf(var + 1e-5f);
    }
    __syncthreads();
    const float mean = smean, rstd = srstd;
#pragma unroll
    for (int it = 0; it < 2; it++) {
        int c = threadIdx.x + it * 256;
        y[(size_t)row * DIM + c] = (v[it] - mean) * rstd * g[c] + b[c];
    }
}

// ---------------- TF32 flash attention, cp.async double-buffered K/V ----------------
// grid = (17 q-tiles of 128, 8 heads, 4 batch), block 256 (8 warps x 16 q-rows).
// K stored ROW-major [key][d] pitch 68: b-frag bank = 4r+j (conflict-free).
// V row-major [key][d] pitch 72: b-frag bank = 8j+r (conflict-free).
// P never hits smem: c-layout -> a-frag via warp shuffles.
#define ATP 68
#define KSP 68
#define VSP 72
#define NKT 33   // ceil(2049/64)
#define KVBUF (64 * KSP + 64 * VSP)              // per K+V buffer (floats)
#define ATT_SMEM ((128 * ATP + 2 * KVBUF) * 4)   // 106496 bytes

__global__ __launch_bounds__(256, 2) void attn_tf32(
    const float* __restrict__ qkv, const int* __restrict__ lens,
    float* __restrict__ o)
{
    extern __shared__ float sma[];
    float* Qs  = sma;                       // [128][ATP]
    float* Ks0 = Qs + 128 * ATP;            // [64][KSP]
    float* Vs0 = Ks0 + 64 * KSP;            // [64][VSP]
    float* Ks1 = Vs0 + 64 * VSP;
    float* Vs1 = Ks1 + 64 * KSP;

    const int tid  = threadIdx.x;
    const int lane = tid & 31;
    const int warp = tid >> 5;
    const int wq   = warp * 16;
    const int r    = lane >> 2;
    const int j    = lane & 3;

    const int qt = blockIdx.x, h = blockIdx.y, b = blockIdx.z;
    const int qbase = qt * 128;
    const int len1  = lens[b] + 1;
    const float* qkv_b = qkv + (size_t)b * N1 * H3;

    // ---- stage Q tile (plain loads; once per block) ----
#pragma unroll
    for (int i = 0; i < 8; i++) {
        int q  = i * 16 + (tid >> 4);
        int d0 = (tid & 15) * 4;
        int qg = qbase + q;
        float4 v = (qg < N1)
            ? *(const float4*)(qkv_b + (size_t)qg * H3 + h * 64 + d0)
            : make_float4(0.f, 0.f, 0.f, 0.f);
        *(float4*)&Qs[q * ATP + d0] = v;
    }

    const int kv_key = tid >> 4;         // 0..15 (x4 iters of +16)
    const int kv_d0  = (tid & 15) * 4;   // 0..60

    // issue K/V tile kt -> buffer p
    {
        // tile 0 -> buf 0
#pragma unroll
        for (int i = 0; i < 4; i++) {
            int key = i * 16 + kv_key;
            int kg  = key;               // kbase = 0
            bool vd = kg < N1;
            const float* base = qkv_b + (size_t)(vd ? kg : 0) * H3 + h * 64 + kv_d0;
            cp16(smem_u32(&Ks0[key * KSP + kv_d0]), base + 512,  vd);
            cp16(smem_u32(&Vs0[key * VSP + kv_d0]), base + 1024, vd);
        }
        cp_commit();
    }

    const int row0g = qbase + wq + r;
    const int row1g = row0g + 8;
    const bool q0pad = row0g >= len1;
    const bool q1pad = row1g >= len1;
    const int psrc0 = (lane & 28) + (j >> 1);   // shfl source lanes (constant)
    const int psrc1 = psrc0 + 2;
    const bool podd = (j & 1);

    float oacc[8][4];
#pragma unroll
    for (int nt = 0; nt < 8; nt++)
#pragma unroll
        for (int q = 0; q < 4; q++) oacc[nt][q] = 0.f;
    float m0 = -1e30f, m1 = -1e30f, l0 = 0.f, l1 = 0.f;

    for (int kt = 0; kt < NKT; kt++) {
        const int kbase = kt * 64;
        cp_wait0();
        __syncthreads();   // K/V[kt] visible; all prior reads of the other buffer done

        const float* Ksp = (kt & 1) ? Ks1 : Ks0;
        const float* Vsp = (kt & 1) ? Vs1 : Vs0;

        if (kt + 1 < NKT) {
            const int nb = (kt + 1) * 64;
            float* Kd = (kt & 1) ? Ks0 : Ks1;
            float* Vd = (kt & 1) ? Vs0 : Vs1;
#pragma unroll
            for (int i = 0; i < 4; i++) {
                int key = i * 16 + kv_key;
                int kg  = nb + key;
                bool vd = kg < N1;
                const float* base = qkv_b + (size_t)(vd ? kg : 0) * H3 + h * 64 + kv_d0;
                cp16(smem_u32(&Kd[key * KSP + kv_d0]), base + 512,  vd);
                cp16(smem_u32(&Vd[key * VSP + kv_d0]), base + 1024, vd);
            }
            cp_commit();
        }

        // ---- S = Q K^T ----
        float sacc[8][4];
#pragma unroll
        for (int nt = 0; nt < 8; nt++)
#pragma unroll
            for (int q = 0; q < 4; q++) sacc[nt][q] = 0.f;
#pragma unroll
        for (int kk = 0; kk < 64; kk += 8) {
            uint32_t af[4];
            af[0] = __float_as_uint(Qs[(wq + r    ) * ATP + kk + j    ]);
            af[1] = __float_as_uint(Qs[(wq + r + 8) * ATP + kk + j    ]);
            af[2] = __float_as_uint(Qs[(wq + r    ) * ATP + kk + j + 4]);
            af[3] = __float_as_uint(Qs[(wq + r + 8) * ATP + kk + j + 4]);
#pragma unroll
            for (int nt = 0; nt < 8; nt++) {
                uint32_t b0 = __float_as_uint(Ksp[(nt * 8 + r) * KSP + kk + j    ]);
                uint32_t b1 = __float_as_uint(Ksp[(nt * 8 + r) * KSP + kk + j + 4]);
                mma8(sacc[nt], af, b0, b1);
            }
        }

        // ---- scale + mask (fast path when whole tile valid & unmasked) ----
        if (kbase + 64 <= len1) {
#pragma unroll
            for (int nt = 0; nt < 8; nt++)
#pragma unroll
                for (int q = 0; q < 4; q++) sacc[nt][q] *= ATT_SCALE;
        } else {
#pragma unroll
            for (int nt = 0; nt < 8; nt++) {
#pragma unroll
                for (int cc = 0; cc < 2; cc++) {
                    int kg = kbase + nt * 8 + 2 * j + cc;
                    bool kinv = (kg >= N1);
                    bool kpad = (kg >= len1);
                    sacc[nt][cc]     = (kinv || (q0pad && kpad)) ? -1e30f : sacc[nt][cc]     * ATT_SCALE;
                    sacc[nt][2 + cc] = (kinv || (q1pad && kpad)) ? -1e30f : sacc[nt][2 + cc] * ATT_SCALE;
                }
            }
        }

        // ---- online softmax (warp-local, 4-lane row groups) ----
        float mx0 = -1e30f, mx1 = -1e30f;
#pragma unroll
        for (int nt = 0; nt < 8; nt++) {
            mx0 = fmaxf(mx0, fmaxf(sacc[nt][0], sacc[nt][1]));
            mx1 = fmaxf(mx1, fmaxf(sacc[nt][2], sacc[nt][3]));
        }
        mx0 = fmaxf(mx0, __shfl_xor_sync(0xffffffffu, mx0, 1));
        mx0 = fmaxf(mx0, __shfl_xor_sync(0xffffffffu, mx0, 2));
        mx1 = fmaxf(mx1, __shfl_xor_sync(0xffffffffu, mx1, 1));
        mx1 = fmaxf(mx1, __shfl_xor_sync(0xffffffffu, mx1, 2));
        float mn0 = fmaxf(m0, mx0), mn1 = fmaxf(m1, mx1);
        float f0 = __expf(m0 - mn0), f1 = __expf(m1 - mn1);
        m0 = mn0; m1 = mn1;
        float s0 = 0.f, s1 = 0.f;
#pragma unroll
        for (int nt = 0; nt < 8; nt++) {
#pragma unroll
            for (int cc = 0; cc < 2; cc++) {
                float p0 = __expf(sacc[nt][cc]     - m0);
                float p1 = __expf(sacc[nt][2 + cc] - m1);
                sacc[nt][cc] = p0;  sacc[nt][2 + cc] = p1;
                s0 += p0; s1 += p1;
            }
        }
        s0 += __shfl_xor_sync(0xffffffffu, s0, 1);
        s0 += __shfl_xor_sync(0xffffffffu, s0, 2);
        s1 += __shfl_xor_sync(0xffffffffu, s1, 1);
        s1 += __shfl_xor_sync(0xffffffffu, s1, 2);
        l0 = l0 * f0 + s0;
        l1 = l1 * f1 + s1;
#pragma unroll
        for (int nt = 0; nt < 8; nt++) {
            oacc[nt][0] *= f0; oacc[nt][1] *= f0;
            oacc[nt][2] *= f1; oacc[nt][3] *= f1;
        }

        // ---- PV: P a-frags via warp shuffles (no smem round-trip) ----
#pragma unroll
        for (int kk = 0; kk < 64; kk += 8) {
            const int np = kk >> 3;
            float t0 = sacc[np][0], t1 = sacc[np][1];
            float t2 = sacc[np][2], t3 = sacc[np][3];
            float s00 = __shfl_sync(0xffffffffu, t0, psrc0);
            float s10 = __shfl_sync(0xffffffffu, t1, psrc0);
            float s02 = __shfl_sync(0xffffffffu, t2, psrc0);
            float s12 = __shfl_sync(0xffffffffu, t3, psrc0);
            float s01 = __shfl_sync(0xffffffffu, t0, psrc1);
            float s11 = __shfl_sync(0xffffffffu, t1, psrc1);
            float s03 = __shfl_sync(0xffffffffu, t2, psrc1);
            float s13 = __shfl_sync(0xffffffffu, t3, psrc1);
            uint32_t af[4];
            af[0] = __float_as_uint(podd ? s10 : s00);   // P[r   ][kk+j]
            af[1] = __float_as_uint(podd ? s12 : s02);   // P[r+8 ][kk+j]
            af[2] = __float_as_uint(podd ? s11 : s01);   // P[r   ][kk+j+4]
            af[3] = __float_as_uint(podd ? s13 : s03);   // P[r+8 ][kk+j+4]
#pragma unroll
            for (int nt = 0; nt < 8; nt++) {
                uint32_t b0 = __float_as_uint(Vsp[(kk + j    ) * VSP + nt * 8 + r]);
                uint32_t b1 = __float_as_uint(Vsp[(kk + j + 4) * VSP + nt * 8 + r]);
                mma8(oacc[nt], af, b0, b1);
            }
        }
    }

    // ---- normalize + write O ----
    float inv0 = 1.f / l0, inv1 = 1.f / l1;
    float* ob = o + (size_t)b * N1 * DIM + h * 64;
    if (row0g < N1) {
#pragma unroll
        for (int nt = 0; nt < 8; nt++)
            *(float2*)&ob[(size_t)row0g * DIM + nt * 8 + 2 * j] =
                make_float2(oacc[nt][0] * inv0, oacc[nt][1] * inv0);
    }
    if (row1g < N1) {
#pragma unroll
        for (int nt = 0; nt < 8; nt++)
            *(float2*)&ob[(size_t)row1g * DIM + nt * 8 + 2 * j] =
                make_float2(oacc[nt][2] * inv1, oacc[nt][3] * inv1);
    }
}

// ---------------- final LN + classifier head (cls token only) ----------------
__global__ __launch_bounds__(256) void head_kernel(
    const float* __restrict__ x, const float* __restrict__ g,
    const float* __restrict__ bb, const float* __restrict__ hw,
    const float* __restrict__ hb, float* __restrict__ out)
{
    const int b = blockIdx.x;
    const float* xr = x + (size_t)b * N1 * DIM;
    float v[2];
    float s = 0.f, s2 = 0.f;
#pragma unroll
    for (int it = 0; it < 2; it++) {
        v[it] = xr[threadIdx.x + it * 256];
        s += v[it]; s2 += v[it] * v[it];
    }
#pragma unroll
    for (int off = 16; off; off >>= 1) {
        s  += __shfl_xor_sync(0xffffffffu, s,  off);
        s2 += __shfl_xor_sync(0xffffffffu, s2, off);
    }
    __shared__ float rs[8], rs2[8];
    __shared__ float smean, srstd;
    const int w = threadIdx.x >> 5;
    if ((threadIdx.x & 31) == 0) { rs[w] = s; rs2[w] = s2; }
    __syncthreads();
    if (threadIdx.x == 0) {
        float a = 0.f, a2 = 0.f;
        for (int i = 0; i < 8; i++) { a += rs[i]; a2 += rs2[i]; }
        float mean = a * (1.f / DIM);
        float var  = a2 * (1.f / DIM) - mean * mean;
        smean = mean;
        srstd = rsqrtf(var + 1e-5f);
    }
    __syncthreads();
    const float mean = smean, rstd = srstd;

    float d0 = 0.f, d1 = 0.f;
#pragma unroll
    for (int it = 0; it < 2; it++) {
        int c = threadIdx.x + it * 256;
        float xn = (v[it] - mean) * rstd * g[c] + bb[c];
        d0 += xn * hw[2 * c + 0];
        d1 += xn * hw[2 * c + 1];
    }
#pragma unroll
    for (int off = 16; off; off >>= 1) {
        d0 += __shfl_xor_sync(0xffffffffu, d0, off);
        d1 += __shfl_xor_sync(0xffffffffu, d1, off);
    }
    __syncthreads();
    if ((threadIdx.x & 31) == 0) { rs[w] = d0; rs2[w] = d1; }
    __syncthreads();
    if (threadIdx.x == 0) {
        float a0 = 0.f, a1 = 0.f;
        for (int i = 0; i < 8; i++) { a0 += rs[i]; a1 += rs2[i]; }
        out[b * 2 + 0] = a0 + hb[0];
        out[b * 2 + 1] = a1 + hb[1];
    }
}

// ---------------- launch ----------------
extern "C" void kernel_launch(void* const* d_in, const int* in_sizes, int n_in,
                              void* d_out, int out_size)
{
    const float* x      = (const float*)d_in[0];
    const int*   lens   = (const int*)  d_in[1];
    const float* cls    = (const float*)d_in[2];
    const float* fc_w   = (const float*)d_in[3];
    const float* fc_b   = (const float*)d_in[4];
    const float* ln1_g  = (const float*)d_in[5];
    const float* ln1_b  = (const float*)d_in[6];
    const float* qkv_w  = (const float*)d_in[7];
    const float* out_w  = (const float*)d_in[8];
    const float* out_b  = (const float*)d_in[9];
    const float* ln2_g  = (const float*)d_in[10];
    const float* ln2_b  = (const float*)d_in[11];
    const float* ff1_w  = (const float*)d_in[12];
    const float* ff1_b  = (const float*)d_in[13];
    const float* ff2_w  = (const float*)d_in[14];
    const float* ff2_b  = (const float*)d_in[15];
    const float* lnf_g  = (const float*)d_in[16];
    const float* lnf_b  = (const float*)d_in[17];
    const float* head_w = (const float*)d_in[18];
    const float* head_b = (const float*)d_in[19];
    float* out = (float*)d_out;

    float *gx, *gxn, *gqkv, *go, *gh;
    cudaGetSymbolAddress((void**)&gx,   g_x);
    cudaGetSymbolAddress((void**)&gxn,  g_xn);
    cudaGetSymbolAddress((void**)&gqkv, g_qkv);
    cudaGetSymbolAddress((void**)&go,   g_o);
    cudaGetSymbolAddress((void**)&gh,   g_h);

    cudaFuncSetAttribute(sgemm_tf32, cudaFuncAttributeMaxDynamicSharedMemorySize, GEMM_SMEM);
    cudaFuncSetAttribute(attn_tf32,  cudaFuncAttributeMaxDynamicSharedMemorySize, ATT_SMEM);

    // cls rows
    cls_fill_kernel<<<BATCH, DIM>>>(cls, gx);

    // fc + GELU, remapped into cls-offset layout: M=8192, N=512, K=768
    sgemm_tf32<<<dim3(DIM / 64, (BATCH * NTOK + 127) / 128), 256, GEMM_SMEM>>>(
        x, fc_w, fc_b, nullptr, gx, BATCH * NTOK, DIM, DIN, /*mode=*/2, /*remap=*/1);

    const int gy = (ROWS_TOT + 127) / 128;   // 65
    for (int l = 0; l < DEPTH; l++) {
        ln_kernel<<<ROWS_TOT, 256>>>(gx, ln1_g + l * DIM, ln1_b + l * DIM, gxn);
        sgemm_tf32<<<dim3(H3 / 64, gy), 256, GEMM_SMEM>>>(
            gxn, qkv_w + (size_t)l * DIM * H3, nullptr, nullptr, gqkv,
            ROWS_TOT, H3, DIM, 0, 0);
        attn_tf32<<<dim3((N1 + 127) / 128, 8, BATCH), 256, ATT_SMEM>>>(gqkv, lens, go);
        sgemm_tf32<<<dim3(DIM / 64, gy), 256, GEMM_SMEM>>>(
            go, out_w + (size_t)l * DIM * DIM, out_b + l * DIM, gx, gx,
            ROWS_TOT, DIM, DIM, 3, 0);
        ln_kernel<<<ROWS_TOT, 256>>>(gx, ln2_g + l * DIM, ln2_b + l * DIM, gxn);
        sgemm_tf32<<<dim3(DIM / 64, gy), 256, GEMM_SMEM>>>(
            gxn, ff1_w + (size_t)l * DIM * DIM, ff1_b + l * DIM, nullptr, gh,
            ROWS_TOT, DIM, DIM, 2, 0);
        sgemm_tf32<<<dim3(DIM / 64, gy), 256, GEMM_SMEM>>>(
            gh, ff2_w + (size_t)l * DIM * DIM, ff2_b + l * DIM, gx, gx,
            ROWS_TOT, DIM, DIM, 3, 0);
    }

    head_kernel<<<BATCH, 256>>>(gx, lnf_g, lnf_b, head_w, head_b, out);
}

// round 13
// speedup vs baseline: 4.7616x; 1.0014x over previous
#include <cuda_runtime.h>
#include <math.h>
#include <stdint.h>

// ---------------- problem constants ----------------
#define BATCH 4
#define NTOK  2048
#define N1    2049          // tokens + cls
#define DIN   768
#define DIM   512
#define H3    1536          // 3*H*DH
#define DEPTH 2
#define ROWS_TOT (BATCH * N1)   // 8196
#define ATT_SCALE 0.125f        // 64^-0.5

// ---------------- scratch (device globals; allocation-free) ----------------
__device__ __align__(256) float g_x  [BATCH * N1 * DIM];
__device__ __align__(256) float g_xn [BATCH * N1 * DIM];
__device__ __align__(256) float g_qkv[BATCH * N1 * H3];
__device__ __align__(256) float g_o  [BATCH * N1 * DIM];
__device__ __align__(256) float g_h  [BATCH * N1 * DIM];

// ---------------- helpers ----------------
__device__ __forceinline__ float gelu_exact(float v) {
    return 0.5f * v * (1.0f + erff(v * 0.70710678118654752440f));
}

// D += A(16x8,row) * B(8x8,col)  tf32 (raw fp32 bits; HW truncates), fp32 accum
__device__ __forceinline__ void mma8(float* c, const uint32_t* a, uint32_t b0, uint32_t b1) {
    asm volatile(
        "mma.sync.aligned.m16n8k8.row.col.f32.tf32.tf32.f32 "
        "{%0,%1,%2,%3}, {%4,%5,%6,%7}, {%8,%9}, {%0,%1,%2,%3};"
        : "+f"(c[0]), "+f"(c[1]), "+f"(c[2]), "+f"(c[3])
        : "r"(a[0]), "r"(a[1]), "r"(a[2]), "r"(a[3]), "r"(b0), "r"(b1));
}

__device__ __forceinline__ uint32_t smem_u32(const void* p) {
    return (uint32_t)__cvta_generic_to_shared(p);
}
// 16B async copy, zero-fill when !pred (src not dereferenced when src-size==0)
__device__ __forceinline__ void cp16(uint32_t dst, const void* src, bool pred) {
    asm volatile("cp.async.cg.shared.global [%0], [%1], 16, %2;"
                 :: "r"(dst), "l"(src), "r"(pred ? 16 : 0));
}
__device__ __forceinline__ void cp_commit() { asm volatile("cp.async.commit_group;"); }
__device__ __forceinline__ void cp_wait0()  { asm volatile("cp.async.wait_group 0;"); }

// ---------------- cls token fill ----------------
__global__ void cls_fill_kernel(const float* __restrict__ cls, float* __restrict__ x) {
    x[(size_t)blockIdx.x * N1 * DIM + threadIdx.x] = cls[threadIdx.x];
}

// ---------------- TF32 tensor-core SGEMM, cp.async double-buffered ----------------
// C[M,N] = A[M,K] @ B[K,N]. mode: 0 none, 1 +bias, 2 gelu(.+bias), 3 +bias+res.
// remap: out row r -> r + r/2048 + 1. Block 128x64x32, 8 warps (4m x 2n) of 32x32.
#define BM 128
#define BN 64
#define BK 32
#define AP 36     // a-frag bank = 4r+j (conflict-free)
#define BP 72     // b-frag bank = 8j+r (conflict-free)
#define SBUF (BM * AP + BK * BP)                 // 6912 floats per buffer
#define GEMM_SMEM (2 * SBUF * 4)                 // 55296 bytes

__global__ __launch_bounds__(256, 3) void sgemm_tf32(
    const float* __restrict__ A, const float* __restrict__ B,
    const float* __restrict__ bias, const float* __restrict__ res,
    float* __restrict__ C, int M, int N, int K, int mode, int remap)
{
    extern __shared__ float gsm[];
    float* As0 = gsm;
    float* Bs0 = gsm + BM * AP;
    float* As1 = gsm + SBUF;
    float* Bs1 = As1 + BM * AP;

    const int tid  = threadIdx.x;
    const int lane = tid & 31;
    const int warp = tid >> 5;
    const int wm   = (warp >> 1) * 32;
    const int wn   = (warp & 1) * 32;
    const int r    = lane >> 2;
    const int j    = lane & 3;
    const int row0 = blockIdx.y * BM;
    const int col0 = blockIdx.x * BN;

    const int a_r = tid >> 3;            // 0..31 (x4 iters of +32)
    const int a_k = (tid & 7) * 4;       // 0..28
    const int b_k = tid >> 4;            // 0..15 (x2 iters of +16)
    const int b_n = (tid & 15) * 4;      // 0..60

    float acc[2][4][4];
#pragma unroll
    for (int mt = 0; mt < 2; mt++)
#pragma unroll
        for (int nt = 0; nt < 4; nt++)
#pragma unroll
            for (int q = 0; q < 4; q++) acc[mt][nt][q] = 0.f;

    // stage tile 0
    {
        float* Ad = As0; float* Bd = Bs0;
#pragma unroll
        for (int i = 0; i < 4; i++) {
            int grow = row0 + i * 32 + a_r;
            cp16(smem_u32(&Ad[(i * 32 + a_r) * AP + a_k]),
                 A + (size_t)(grow < M ? grow : 0) * K + a_k, grow < M);
        }
#pragma unroll
        for (int i = 0; i < 2; i++)
            cp16(smem_u32(&Bd[(i * 16 + b_k) * BP + b_n]),
                 B + (size_t)(i * 16 + b_k) * N + col0 + b_n, true);
        cp_commit();
    }

    const int KB = K / BK;
    for (int kb = 0; kb < KB; kb++) {
        cp_wait0();
        __syncthreads();

        const float* Asp = (kb & 1) ? As1 : As0;
        const float* Bsp = (kb & 1) ? Bs1 : Bs0;

        if (kb + 1 < KB) {
            const int k0 = (kb + 1) * BK;
            float* Ad = (kb & 1) ? As0 : As1;
            float* Bd = (kb & 1) ? Bs0 : Bs1;
#pragma unroll
            for (int i = 0; i < 4; i++) {
                int grow = row0 + i * 32 + a_r;
                cp16(smem_u32(&Ad[(i * 32 + a_r) * AP + a_k]),
                     A + (size_t)(grow < M ? grow : 0) * K + k0 + a_k, grow < M);
            }
#pragma unroll
            for (int i = 0; i < 2; i++)
                cp16(smem_u32(&Bd[(i * 16 + b_k) * BP + b_n]),
                     B + (size_t)(k0 + i * 16 + b_k) * N + col0 + b_n, true);
            cp_commit();
        }

#pragma unroll
        for (int kk = 0; kk < BK; kk += 8) {
            uint32_t af[2][4];
#pragma unroll
            for (int mt = 0; mt < 2; mt++) {
                int mb = wm + mt * 16;
                af[mt][0] = __float_as_uint(Asp[(mb + r    ) * AP + kk + j    ]);
                af[mt][1] = __float_as_uint(Asp[(mb + r + 8) * AP + kk + j    ]);
                af[mt][2] = __float_as_uint(Asp[(mb + r    ) * AP + kk + j + 4]);
                af[mt][3] = __float_as_uint(Asp[(mb + r + 8) * AP + kk + j + 4]);
            }
#pragma unroll
            for (int nt = 0; nt < 4; nt++) {
                uint32_t b0 = __float_as_uint(Bsp[(kk + j    ) * BP + wn + nt * 8 + r]);
                uint32_t b1 = __float_as_uint(Bsp[(kk + j + 4) * BP + wn + nt * 8 + r]);
                mma8(acc[0][nt], af[0], b0, b1);
                mma8(acc[1][nt], af[1], b0, b1);
            }
        }
    }

#pragma unroll
    for (int mt = 0; mt < 2; mt++) {
#pragma unroll
        for (int half = 0; half < 2; half++) {
            int grow = row0 + wm + mt * 16 + r + half * 8;
            if (grow >= M) continue;
            size_t orow = remap ? (size_t)(grow + grow / 2048 + 1) : (size_t)grow;
#pragma unroll
            for (int nt = 0; nt < 4; nt++) {
                int gc = col0 + wn + nt * 8 + 2 * j;
                float v0 = acc[mt][nt][half * 2 + 0];
                float v1 = acc[mt][nt][half * 2 + 1];
                if (mode >= 1) { v0 += bias[gc]; v1 += bias[gc + 1]; }
                if (mode == 2) { v0 = gelu_exact(v0); v1 = gelu_exact(v1); }
                float* cp = C + orow * N + gc;
                if (mode == 3) {
                    const float* rp = res + orow * N + gc;
                    v0 += rp[0]; v1 += rp[1];
                }
                *(float2*)cp = make_float2(v0, v1);
            }
        }
    }
}

// ---------------- LayerNorm (one block per row, D=512) ----------------
__global__ __launch_bounds__(256) void ln_kernel(
    const float* __restrict__ x, const float* __restrict__ g,
    const float* __restrict__ b, float* __restrict__ y)
{
    const int row = blockIdx.x;
    const float* xr = x + (size_t)row * DIM;
    float v[2];
    float s = 0.f, s2 = 0.f;
#pragma unroll
    for (int it = 0; it < 2; it++) {
        v[it] = xr[threadIdx.x + it * 256];
        s += v[it]; s2 += v[it] * v[it];
    }
#pragma unroll
    for (int off = 16; off; off >>= 1) {
        s  += __shfl_xor_sync(0xffffffffu, s,  off);
        s2 += __shfl_xor_sync(0xffffffffu, s2, off);
    }
    __shared__ float rs[8], rs2[8];
    __shared__ float smean, srstd;
    const int w = threadIdx.x >> 5;
    if ((threadIdx.x & 31) == 0) { rs[w] = s; rs2[w] = s2; }
    __syncthreads();
    if (threadIdx.x == 0) {
        float a = 0.f, a2 = 0.f;
        for (int i = 0; i < 8; i++) { a += rs[i]; a2 += rs2[i]; }
        float mean = a * (1.f / DIM);
        float var  = a2 * (1.f / DIM) - mean * mean;
        smean = mean;
        srstd = rsqrtf(var + 1e-5f);
    }
    __syncthreads();
    const float mean = smean, rstd = srstd;
#pragma unroll
    for (int it = 0; it < 2; it++) {
        int c = threadIdx.x + it * 256;
        y[(size_t)row * DIM + c] = (v[it] - mean) * rstd * g[c] + b[c];
    }
}

// ---------------- TF32 flash attention, cp.async double-buffered K/V ----------------
// grid = (17 q-tiles of 128, 8 heads, 4 batch), block 256 (8 warps x 16 q-rows).
// K stored ROW-major [key][d] pitch 68: b-frag bank = 4r+j (conflict-free).
// V row-major [key][d] pitch 72: b-frag bank = 8j+r (conflict-free).
// P never hits smem: c-layout -> a-frag via warp shuffles.
#define ATP 68
#define KSP 68
#define VSP 72
#define NKT 33   // ceil(2049/64)
#define KVBUF (64 * KSP + 64 * VSP)              // per K+V buffer (floats)
#define ATT_SMEM ((128 * ATP + 2 * KVBUF) * 4)   // 106496 bytes

__global__ __launch_bounds__(256, 2) void attn_tf32(
    const float* __restrict__ qkv, const int* __restrict__ lens,
    float* __restrict__ o)
{
    extern __shared__ float sma[];
    float* Qs  = sma;                       // [128][ATP]
    float* Ks0 = Qs + 128 * ATP;            // [64][KSP]
    float* Vs0 = Ks0 + 64 * KSP;            // [64][VSP]
    float* Ks1 = Vs0 + 64 * VSP;
    float* Vs1 = Ks1 + 64 * KSP;

    const int tid  = threadIdx.x;
    const int lane = tid & 31;
    const int warp = tid >> 5;
    const int wq   = warp * 16;
    const int r    = lane >> 2;
    const int j    = lane & 3;

    const int qt = blockIdx.x, h = blockIdx.y, b = blockIdx.z;
    const int qbase = qt * 128;
    const int len1  = lens[b] + 1;
    const float* qkv_b = qkv + (size_t)b * N1 * H3;

    // ---- stage Q tile (plain loads; once per block) ----
#pragma unroll
    for (int i = 0; i < 8; i++) {
        int q  = i * 16 + (tid >> 4);
        int d0 = (tid & 15) * 4;
        int qg = qbase + q;
        float4 v = (qg < N1)
            ? *(const float4*)(qkv_b + (size_t)qg * H3 + h * 64 + d0)
            : make_float4(0.f, 0.f, 0.f, 0.f);
        *(float4*)&Qs[q * ATP + d0] = v;
    }

    const int kv_key = tid >> 4;         // 0..15 (x4 iters of +16)
    const int kv_d0  = (tid & 15) * 4;   // 0..60

    // issue K/V tile kt -> buffer p
    {
        // tile 0 -> buf 0
#pragma unroll
        for (int i = 0; i < 4; i++) {
            int key = i * 16 + kv_key;
            int kg  = key;               // kbase = 0
            bool vd = kg < N1;
            const float* base = qkv_b + (size_t)(vd ? kg : 0) * H3 + h * 64 + kv_d0;
            cp16(smem_u32(&Ks0[key * KSP + kv_d0]), base + 512,  vd);
            cp16(smem_u32(&Vs0[key * VSP + kv_d0]), base + 1024, vd);
        }
        cp_commit();
    }

    const int row0g = qbase + wq + r;
    const int row1g = row0g + 8;
    const bool q0pad = row0g >= len1;
    const bool q1pad = row1g >= len1;
    const int psrc0 = (lane & 28) + (j >> 1);   // shfl source lanes (constant)
    const int psrc1 = psrc0 + 2;
    const bool podd = (j & 1);

    float oacc[8][4];
#pragma unroll
    for (int nt = 0; nt < 8; nt++)
#pragma unroll
        for (int q = 0; q < 4; q++) oacc[nt][q] = 0.f;
    float m0 = -1e30f, m1 = -1e30f, l0 = 0.f, l1 = 0.f;

    for (int kt = 0; kt < NKT; kt++) {
        const int kbase = kt * 64;
        cp_wait0();
        __syncthreads();   // K/V[kt] visible; all prior reads of the other buffer done

        const float* Ksp = (kt & 1) ? Ks1 : Ks0;
        const float* Vsp = (kt & 1) ? Vs1 : Vs0;

        if (kt + 1 < NKT) {
            const int nb = (kt + 1) * 64;
            float* Kd = (kt & 1) ? Ks0 : Ks1;
            float* Vd = (kt & 1) ? Vs0 : Vs1;
#pragma unroll
            for (int i = 0; i < 4; i++) {
                int key = i * 16 + kv_key;
                int kg  = nb + key;
                bool vd = kg < N1;
                const float* base = qkv_b + (size_t)(vd ? kg : 0) * H3 + h * 64 + kv_d0;
                cp16(smem_u32(&Kd[key * KSP + kv_d0]), base + 512,  vd);
                cp16(smem_u32(&Vd[key * VSP + kv_d0]), base + 1024, vd);
            }
            cp_commit();
        }

        // ---- S = Q K^T ----
        float sacc[8][4];
#pragma unroll
        for (int nt = 0; nt < 8; nt++)
#pragma unroll
            for (int q = 0; q < 4; q++) sacc[nt][q] = 0.f;
#pragma unroll
        for (int kk = 0; kk < 64; kk += 8) {
            uint32_t af[4];
            af[0] = __float_as_uint(Qs[(wq + r    ) * ATP + kk + j    ]);
            af[1] = __float_as_uint(Qs[(wq + r + 8) * ATP + kk + j    ]);
            af[2] = __float_as_uint(Qs[(wq + r    ) * ATP + kk + j + 4]);
            af[3] = __float_as_uint(Qs[(wq + r + 8) * ATP + kk + j + 4]);
#pragma unroll
            for (int nt = 0; nt < 8; nt++) {
                uint32_t b0 = __float_as_uint(Ksp[(nt * 8 + r) * KSP + kk + j    ]);
                uint32_t b1 = __float_as_uint(Ksp[(nt * 8 + r) * KSP + kk + j + 4]);
                mma8(sacc[nt], af, b0, b1);
            }
        }

        // ---- scale + mask (fast path when whole tile valid & unmasked) ----
        if (kbase + 64 <= len1) {
#pragma unroll
            for (int nt = 0; nt < 8; nt++)
#pragma unroll
                for (int q = 0; q < 4; q++) sacc[nt][q] *= ATT_SCALE;
        } else {
#pragma unroll
            for (int nt = 0; nt < 8; nt++) {
#pragma unroll
                for (int cc = 0; cc < 2; cc++) {
                    int kg = kbase + nt * 8 + 2 * j + cc;
                    bool kinv = (kg >= N1);
                    bool kpad = (kg >= len1);
                    sacc[nt][cc]     = (kinv || (q0pad && kpad)) ? -1e30f : sacc[nt][cc]     * ATT_SCALE;
                    sacc[nt][2 + cc] = (kinv || (q1pad && kpad)) ? -1e30f : sacc[nt][2 + cc] * ATT_SCALE;
                }
            }
        }

        // ---- online softmax (warp-local, 4-lane row groups) ----
        float mx0 = -1e30f, mx1 = -1e30f;
#pragma unroll
        for (int nt = 0; nt < 8; nt++) {
            mx0 = fmaxf(mx0, fmaxf(sacc[nt][0], sacc[nt][1]));
            mx1 = fmaxf(mx1, fmaxf(sacc[nt][2], sacc[nt][3]));
        }
        mx0 = fmaxf(mx0, __shfl_xor_sync(0xffffffffu, mx0, 1));
        mx0 = fmaxf(mx0, __shfl_xor_sync(0xffffffffu, mx0, 2));
        mx1 = fmaxf(mx1, __shfl_xor_sync(0xffffffffu, mx1, 1));
        mx1 = fmaxf(mx1, __shfl_xor_sync(0xffffffffu, mx1, 2));
        float mn0 = fmaxf(m0, mx0), mn1 = fmaxf(m1, mx1);
        float f0 = __expf(m0 - mn0), f1 = __expf(m1 - mn1);
        m0 = mn0; m1 = mn1;
        float s0 = 0.f, s1 = 0.f;
#pragma unroll
        for (int nt = 0; nt < 8; nt++) {
#pragma unroll
            for (int cc = 0; cc < 2; cc++) {
                float p0 = __expf(sacc[nt][cc]     - m0);
                float p1 = __expf(sacc[nt][2 + cc] - m1);
                sacc[nt][cc] = p0;  sacc[nt][2 + cc] = p1;
                s0 += p0; s1 += p1;
            }
        }
        s0 += __shfl_xor_sync(0xffffffffu, s0, 1);
        s0 += __shfl_xor_sync(0xffffffffu, s0, 2);
        s1 += __shfl_xor_sync(0xffffffffu, s1, 1);
        s1 += __shfl_xor_sync(0xffffffffu, s1, 2);
        l0 = l0 * f0 + s0;
        l1 = l1 * f1 + s1;
#pragma unroll
        for (int nt = 0; nt < 8; nt++) {
            oacc[nt][0] *= f0; oacc[nt][1] *= f0;
            oacc[nt][2] *= f1; oacc[nt][3] *= f1;
        }

        // ---- PV: P a-frags via warp shuffles (no smem round-trip) ----
#pragma unroll
        for (int kk = 0; kk < 64; kk += 8) {
            const int np = kk >> 3;
            float t0 = sacc[np][0], t1 = sacc[np][1];
            float t2 = sacc[np][2], t3 = sacc[np][3];
            float s00 = __shfl_sync(0xffffffffu, t0, psrc0);
            float s10 = __shfl_sync(0xffffffffu, t1, psrc0);
            float s02 = __shfl_sync(0xffffffffu, t2, psrc0);
            float s12 = __shfl_sync(0xffffffffu, t3, psrc0);
            float s01 = __shfl_sync(0xffffffffu, t0, psrc1);
            float s11 = __shfl_sync(0xffffffffu, t1, psrc1);
            float s03 = __shfl_sync(0xffffffffu, t2, psrc1);
            float s13 = __shfl_sync(0xffffffffu, t3, psrc1);
            uint32_t af[4];
            af[0] = __float_as_uint(podd ? s10 : s00);   // P[r   ][kk+j]
            af[1] = __float_as_uint(podd ? s12 : s02);   // P[r+8 ][kk+j]
            af[2] = __float_as_uint(podd ? s11 : s01);   // P[r   ][kk+j+4]
            af[3] = __float_as_uint(podd ? s13 : s03);   // P[r+8 ][kk+j+4]
#pragma unroll
            for (int nt = 0; nt < 8; nt++) {
                uint32_t b0 = __float_as_uint(Vsp[(kk + j    ) * VSP + nt * 8 + r]);
                uint32_t b1 = __float_as_uint(Vsp[(kk + j + 4) * VSP + nt * 8 + r]);
                mma8(oacc[nt], af, b0, b1);
            }
        }
    }

    // ---- normalize + write O ----
    float inv0 = 1.f / l0, inv1 = 1.f / l1;
    float* ob = o + (size_t)b * N1 * DIM + h * 64;
    if (row0g < N1) {
#pragma unroll
        for (int nt = 0; nt < 8; nt++)
            *(float2*)&ob[(size_t)row0g * DIM + nt * 8 + 2 * j] =
                make_float2(oacc[nt][0] * inv0, oacc[nt][1] * inv0);
    }
    if (row1g < N1) {
#pragma unroll
        for (int nt = 0; nt < 8; nt++)
            *(float2*)&ob[(size_t)row1g * DIM + nt * 8 + 2 * j] =
                make_float2(oacc[nt][2] * inv1, oacc[nt][3] * inv1);
    }
}

// ---------------- final LN + classifier head (cls token only) ----------------
__global__ __launch_bounds__(256) void head_kernel(
    const float* __restrict__ x, const float* __restrict__ g,
    const float* __restrict__ bb, const float* __restrict__ hw,
    const float* __restrict__ hb, float* __restrict__ out)
{
    const int b = blockIdx.x;
    const float* xr = x + (size_t)b * N1 * DIM;
    float v[2];
    float s = 0.f, s2 = 0.f;
#pragma unroll
    for (int it = 0; it < 2; it++) {
        v[it] = xr[threadIdx.x + it * 256];
        s += v[it]; s2 += v[it] * v[it];
    }
#pragma unroll
    for (int off = 16; off; off >>= 1) {
        s  += __shfl_xor_sync(0xffffffffu, s,  off);
        s2 += __shfl_xor_sync(0xffffffffu, s2, off);
    }
    __shared__ float rs[8], rs2[8];
    __shared__ float smean, srstd;
    const int w = threadIdx.x >> 5;
    if ((threadIdx.x & 31) == 0) { rs[w] = s; rs2[w] = s2; }
    __syncthreads();
    if (threadIdx.x == 0) {
        float a = 0.f, a2 = 0.f;
        for (int i = 0; i < 8; i++) { a += rs[i]; a2 += rs2[i]; }
        float mean = a * (1.f / DIM);
        float var  = a2 * (1.f / DIM) - mean * mean;
        smean = mean;
        srstd = rsqrtf(var + 1e-5f);
    }
    __syncthreads();
    const float mean = smean, rstd = srstd;

    float d0 = 0.f, d1 = 0.f;
#pragma unroll
    for (int it = 0; it < 2; it++) {
        int c = threadIdx.x + it * 256;
        float xn = (v[it] - mean) * rstd * g[c] + bb[c];
        d0 += xn * hw[2 * c + 0];
        d1 += xn * hw[2 * c + 1];
    }
#pragma unroll
    for (int off = 16; off; off >>= 1) {
        d0 += __shfl_xor_sync(0xffffffffu, d0, off);
        d1 += __shfl_xor_sync(0xffffffffu, d1, off);
    }
    __syncthreads();
    if ((threadIdx.x & 31) == 0) { rs[w] = d0; rs2[w] = d1; }
    __syncthreads();
    if (threadIdx.x == 0) {
        float a0 = 0.f, a1 = 0.f;
        for (int i = 0; i < 8; i++) { a0 += rs[i]; a1 += rs2[i]; }
        out[b * 2 + 0] = a0 + hb[0];
        out[b * 2 + 1] = a1 + hb[1];
    }
}

// ---------------- launch ----------------
extern "C" void kernel_launch(void* const* d_in, const int* in_sizes, int n_in,
                              void* d_out, int out_size)
{
    const float* x      = (const float*)d_in[0];
    const int*   lens   = (const int*)  d_in[1];
    const float* cls    = (const float*)d_in[2];
    const float* fc_w   = (const float*)d_in[3];
    const float* fc_b   = (const float*)d_in[4];
    const float* ln1_g  = (const float*)d_in[5];
    const float* ln1_b  = (const float*)d_in[6];
    const float* qkv_w  = (const float*)d_in[7];
    const float* out_w  = (const float*)d_in[8];
    const float* out_b  = (const float*)d_in[9];
    const float* ln2_g  = (const float*)d_in[10];
    const float* ln2_b  = (const float*)d_in[11];
    const float* ff1_w  = (const float*)d_in[12];
    const float* ff1_b  = (const float*)d_in[13];
    const float* ff2_w  = (const float*)d_in[14];
    const float* ff2_b  = (const float*)d_in[15];
    const float* lnf_g  = (const float*)d_in[16];
    const float* lnf_b  = (const float*)d_in[17];
    const float* head_w = (const float*)d_in[18];
    const float* head_b = (const float*)d_in[19];
    float* out = (float*)d_out;

    float *gx, *gxn, *gqkv, *go, *gh;
    cudaGetSymbolAddress((void**)&gx,   g_x);
    cudaGetSymbolAddress((void**)&gxn,  g_xn);
    cudaGetSymbolAddress((void**)&gqkv, g_qkv);
    cudaGetSymbolAddress((void**)&go,   g_o);
    cudaGetSymbolAddress((void**)&gh,   g_h);

    cudaFuncSetAttribute(sgemm_tf32, cudaFuncAttributeMaxDynamicSharedMemorySize, GEMM_SMEM);
    cudaFuncSetAttribute(attn_tf32,  cudaFuncAttributeMaxDynamicSharedMemorySize, ATT_SMEM);

    // cls rows
    cls_fill_kernel<<<BATCH, DIM>>>(cls, gx);

    // fc + GELU, remapped into cls-offset layout: M=8192, N=512, K=768
    sgemm_tf32<<<dim3(DIM / 64, (BATCH * NTOK + 127) / 128), 256, GEMM_SMEM>>>(
        x, fc_w, fc_b, nullptr, gx, BATCH * NTOK, DIM, DIN, /*mode=*/2, /*remap=*/1);

    const int gy = (ROWS_TOT + 127) / 128;   // 65
    for (int l = 0; l < DEPTH; l++) {
        ln_kernel<<<ROWS_TOT, 256>>>(gx, ln1_g + l * DIM, ln1_b + l * DIM, gxn);
        sgemm_tf32<<<dim3(H3 / 64, gy), 256, GEMM_SMEM>>>(
            gxn, qkv_w + (size_t)l * DIM * H3, nullptr, nullptr, gqkv,
            ROWS_TOT, H3, DIM, 0, 0);
        attn_tf32<<<dim3((N1 + 127) / 128, 8, BATCH), 256, ATT_SMEM>>>(gqkv, lens, go);
        sgemm_tf32<<<dim3(DIM / 64, gy), 256, GEMM_SMEM>>>(
            go, out_w + (size_t)l * DIM * DIM, out_b + l * DIM, gx, gx,
            ROWS_TOT, DIM, DIM, 3, 0);
        ln_kernel<<<ROWS_TOT, 256>>>(gx, ln2_g + l * DIM, ln2_b + l * DIM, gxn);
        sgemm_tf32<<<dim3(DIM / 64, gy), 256, GEMM_SMEM>>>(
            gxn, ff1_w + (size_t)l * DIM * DIM, ff1_b + l * DIM, nullptr, gh,
            ROWS_TOT, DIM, DIM, 2, 0);
        sgemm_tf32<<<dim3(DIM / 64, gy), 256, GEMM_SMEM>>>(
            gh, ff2_w + (size_t)l * DIM * DIM, ff2_b + l * DIM, gx, gx,
            ROWS_TOT, DIM, DIM, 3, 0);
    }

    head_kernel<<<BATCH, 256>>>(gx, lnf_g, lnf_b, head_w, head_b, out);
}

// round 14
// speedup vs baseline: 4.7723x; 1.0022x over previous
#include <cuda_runtime.h>
#include <math.h>
#include <stdint.h>

// ---------------- problem constants ----------------
#define BATCH 4
#define NTOK  2048
#define N1    2049          // tokens + cls
#define DIN   768
#define DIM   512
#define H3    1536          // 3*H*DH
#define DEPTH 2
#define ROWS_TOT (BATCH * N1)   // 8196
#define ATT_SCALE 0.125f        // 64^-0.5

// ---------------- scratch (device globals; allocation-free) ----------------
__device__ __align__(256) float g_x  [BATCH * N1 * DIM];
__device__ __align__(256) float g_xn [BATCH * N1 * DIM];
__device__ __align__(256) float g_qkv[BATCH * N1 * H3];
__device__ __align__(256) float g_o  [BATCH * N1 * DIM];
__device__ __align__(256) float g_h  [BATCH * N1 * DIM];

// ---------------- helpers ----------------
__device__ __forceinline__ float gelu_exact(float v) {
    return 0.5f * v * (1.0f + erff(v * 0.70710678118654752440f));
}

// D += A(16x8,row) * B(8x8,col)  tf32 (raw fp32 bits; HW truncates), fp32 accum
__device__ __forceinline__ void mma8(float* c, const uint32_t* a, uint32_t b0, uint32_t b1) {
    asm volatile(
        "mma.sync.aligned.m16n8k8.row.col.f32.tf32.tf32.f32 "
        "{%0,%1,%2,%3}, {%4,%5,%6,%7}, {%8,%9}, {%0,%1,%2,%3};"
        : "+f"(c[0]), "+f"(c[1]), "+f"(c[2]), "+f"(c[3])
        : "r"(a[0]), "r"(a[1]), "r"(a[2]), "r"(a[3]), "r"(b0), "r"(b1));
}

__device__ __forceinline__ uint32_t smem_u32(const void* p) {
    return (uint32_t)__cvta_generic_to_shared(p);
}
// 16B async copy, zero-fill when !pred (src not dereferenced when src-size==0)
__device__ __forceinline__ void cp16(uint32_t dst, const void* src, bool pred) {
    asm volatile("cp.async.cg.shared.global [%0], [%1], 16, %2;"
                 :: "r"(dst), "l"(src), "r"(pred ? 16 : 0));
}
__device__ __forceinline__ void cp_commit() { asm volatile("cp.async.commit_group;"); }
__device__ __forceinline__ void cp_wait0()  { asm volatile("cp.async.wait_group 0;"); }

// ---------------- cls token fill ----------------
__global__ void cls_fill_kernel(const float* __restrict__ cls, float* __restrict__ x) {
    x[(size_t)blockIdx.x * N1 * DIM + threadIdx.x] = cls[threadIdx.x];
}

// ---------------- TF32 tensor-core SGEMM, cp.async double-buffered ----------------
// C[M,N] = A[M,K] @ B[K,N]. mode: 0 none, 1 +bias, 2 gelu(.+bias), 3 +bias+res.
// remap: out row r -> r + r/2048 + 1. Block 128x64x32, 8 warps (4m x 2n) of 32x32.
#define BM 128
#define BN 64
#define BK 32
#define AP 36     // a-frag bank = 4r+j (conflict-free)
#define BP 72     // b-frag bank = 8j+r (conflict-free)
#define SBUF (BM * AP + BK * BP)                 // 6912 floats per buffer
#define GEMM_SMEM (2 * SBUF * 4)                 // 55296 bytes

__global__ __launch_bounds__(256, 3) void sgemm_tf32(
    const float* __restrict__ A, const float* __restrict__ B,
    const float* __restrict__ bias, const float* __restrict__ res,
    float* __restrict__ C, int M, int N, int K, int mode, int remap)
{
    extern __shared__ float gsm[];
    float* As0 = gsm;
    float* Bs0 = gsm + BM * AP;
    float* As1 = gsm + SBUF;
    float* Bs1 = As1 + BM * AP;

    const int tid  = threadIdx.x;
    const int lane = tid & 31;
    const int warp = tid >> 5;
    const int wm   = (warp >> 1) * 32;
    const int wn   = (warp & 1) * 32;
    const int r    = lane >> 2;
    const int j    = lane & 3;
    const int row0 = blockIdx.y * BM;
    const int col0 = blockIdx.x * BN;

    const int a_r = tid >> 3;            // 0..31 (x4 iters of +32)
    const int a_k = (tid & 7) * 4;       // 0..28
    const int b_k = tid >> 4;            // 0..15 (x2 iters of +16)
    const int b_n = (tid & 15) * 4;      // 0..60

    float acc[2][4][4];
#pragma unroll
    for (int mt = 0; mt < 2; mt++)
#pragma unroll
        for (int nt = 0; nt < 4; nt++)
#pragma unroll
            for (int q = 0; q < 4; q++) acc[mt][nt][q] = 0.f;

    // stage tile 0
    {
        float* Ad = As0; float* Bd = Bs0;
#pragma unroll
        for (int i = 0; i < 4; i++) {
            int grow = row0 + i * 32 + a_r;
            cp16(smem_u32(&Ad[(i * 32 + a_r) * AP + a_k]),
                 A + (size_t)(grow < M ? grow : 0) * K + a_k, grow < M);
        }
#pragma unroll
        for (int i = 0; i < 2; i++)
            cp16(smem_u32(&Bd[(i * 16 + b_k) * BP + b_n]),
                 B + (size_t)(i * 16 + b_k) * N + col0 + b_n, true);
        cp_commit();
    }

    const int KB = K / BK;
    for (int kb = 0; kb < KB; kb++) {
        cp_wait0();
        __syncthreads();

        const float* Asp = (kb & 1) ? As1 : As0;
        const float* Bsp = (kb & 1) ? Bs1 : Bs0;

        if (kb + 1 < KB) {
            const int k0 = (kb + 1) * BK;
            float* Ad = (kb & 1) ? As0 : As1;
            float* Bd = (kb & 1) ? Bs0 : Bs1;
#pragma unroll
            for (int i = 0; i < 4; i++) {
                int grow = row0 + i * 32 + a_r;
                cp16(smem_u32(&Ad[(i * 32 + a_r) * AP + a_k]),
                     A + (size_t)(grow < M ? grow : 0) * K + k0 + a_k, grow < M);
            }
#pragma unroll
            for (int i = 0; i < 2; i++)
                cp16(smem_u32(&Bd[(i * 16 + b_k) * BP + b_n]),
                     B + (size_t)(k0 + i * 16 + b_k) * N + col0 + b_n, true);
            cp_commit();
        }

#pragma unroll
        for (int kk = 0; kk < BK; kk += 8) {
            uint32_t af[2][4];
#pragma unroll
            for (int mt = 0; mt < 2; mt++) {
                int mb = wm + mt * 16;
                af[mt][0] = __float_as_uint(Asp[(mb + r    ) * AP + kk + j    ]);
                af[mt][1] = __float_as_uint(Asp[(mb + r + 8) * AP + kk + j    ]);
                af[mt][2] = __float_as_uint(Asp[(mb + r    ) * AP + kk + j + 4]);
                af[mt][3] = __float_as_uint(Asp[(mb + r + 8) * AP + kk + j + 4]);
            }
#pragma unroll
            for (int nt = 0; nt < 4; nt++) {
                uint32_t b0 = __float_as_uint(Bsp[(kk + j    ) * BP + wn + nt * 8 + r]);
                uint32_t b1 = __float_as_uint(Bsp[(kk + j + 4) * BP + wn + nt * 8 + r]);
                mma8(acc[0][nt], af[0], b0, b1);
                mma8(acc[1][nt], af[1], b0, b1);
            }
        }
    }

#pragma unroll
    for (int mt = 0; mt < 2; mt++) {
#pragma unroll
        for (int half = 0; half < 2; half++) {
            int grow = row0 + wm + mt * 16 + r + half * 8;
            if (grow >= M) continue;
            size_t orow = remap ? (size_t)(grow + grow / 2048 + 1) : (size_t)grow;
#pragma unroll
            for (int nt = 0; nt < 4; nt++) {
                int gc = col0 + wn + nt * 8 + 2 * j;
                float v0 = acc[mt][nt][half * 2 + 0];
                float v1 = acc[mt][nt][half * 2 + 1];
                if (mode >= 1) { v0 += bias[gc]; v1 += bias[gc + 1]; }
                if (mode == 2) { v0 = gelu_exact(v0); v1 = gelu_exact(v1); }
                float* cp = C + orow * N + gc;
                if (mode == 3) {
                    const float* rp = res + orow * N + gc;
                    v0 += rp[0]; v1 += rp[1];
                }
                *(float2*)cp = make_float2(v0, v1);
            }
        }
    }
}

// ---------------- LayerNorm (one block per row, D=512) ----------------
__global__ __launch_bounds__(256) void ln_kernel(
    const float* __restrict__ x, const float* __restrict__ g,
    const float* __restrict__ b, float* __restrict__ y)
{
    const int row = blockIdx.x;
    const float* xr = x + (size_t)row * DIM;
    float v[2];
    float s = 0.f, s2 = 0.f;
#pragma unroll
    for (int it = 0; it < 2; it++) {
        v[it] = xr[threadIdx.x + it * 256];
        s += v[it]; s2 += v[it] * v[it];
    }
#pragma unroll
    for (int off = 16; off; off >>= 1) {
        s  += __shfl_xor_sync(0xffffffffu, s,  off);
        s2 += __shfl_xor_sync(0xffffffffu, s2, off);
    }
    __shared__ float rs[8], rs2[8];
    __shared__ float smean, srstd;
    const int w = threadIdx.x >> 5;
    if ((threadIdx.x & 31) == 0) { rs[w] = s; rs2[w] = s2; }
    __syncthreads();
    if (threadIdx.x == 0) {
        float a = 0.f, a2 = 0.f;
        for (int i = 0; i < 8; i++) { a += rs[i]; a2 += rs2[i]; }
        float mean = a * (1.f / DIM);
        float var  = a2 * (1.f / DIM) - mean * mean;
        smean = mean;
        srstd = rsqrtf(var + 1e-5f);
    }
    __syncthreads();
    const float mean = smean, rstd = srstd;
#pragma unroll
    for (int it = 0; it < 2; it++) {
        int c = threadIdx.x + it * 256;
        y[(size_t)row * DIM + c] = (v[it] - mean) * rstd * g[c] + b[c];
    }
}

// ---------------- TF32 flash attention, cp.async double-buffered K/V ----------------
// grid = (17 q-tiles of 128, 8 heads, 4 batch), block 256 (8 warps x 16 q-rows).
// K stored ROW-major [key][d] pitch 68: b-frag bank = 4r+j (conflict-free).
// V row-major [key][d] pitch 72: b-frag bank = 8j+r (conflict-free).
// P never hits smem: c-layout -> a-frag via warp shuffles.
#define ATP 68
#define KSP 68
#define VSP 72
#define NKT 33   // ceil(2049/64)
#define KVBUF (64 * KSP + 64 * VSP)              // per K+V buffer (floats)
#define ATT_SMEM ((128 * ATP + 2 * KVBUF) * 4)   // 106496 bytes

__global__ __launch_bounds__(256, 2) void attn_tf32(
    const float* __restrict__ qkv, const int* __restrict__ lens,
    float* __restrict__ o)
{
    extern __shared__ float sma[];
    float* Qs  = sma;                       // [128][ATP]
    float* Ks0 = Qs + 128 * ATP;            // [64][KSP]
    float* Vs0 = Ks0 + 64 * KSP;            // [64][VSP]
    float* Ks1 = Vs0 + 64 * VSP;
    float* Vs1 = Ks1 + 64 * KSP;

    const int tid  = threadIdx.x;
    const int lane = tid & 31;
    const int warp = tid >> 5;
    const int wq   = warp * 16;
    const int r    = lane >> 2;
    const int j    = lane & 3;

    const int qt = blockIdx.x, h = blockIdx.y, b = blockIdx.z;
    const int qbase = qt * 128;
    const int len1  = lens[b] + 1;
    const float* qkv_b = qkv + (size_t)b * N1 * H3;

    // ---- stage Q tile (plain loads; once per block) ----
#pragma unroll
    for (int i = 0; i < 8; i++) {
        int q  = i * 16 + (tid >> 4);
        int d0 = (tid & 15) * 4;
        int qg = qbase + q;
        float4 v = (qg < N1)
            ? *(const float4*)(qkv_b + (size_t)qg * H3 + h * 64 + d0)
            : make_float4(0.f, 0.f, 0.f, 0.f);
        *(float4*)&Qs[q * ATP + d0] = v;
    }

    const int kv_key = tid >> 4;         // 0..15 (x4 iters of +16)
    const int kv_d0  = (tid & 15) * 4;   // 0..60

    // issue K/V tile kt -> buffer p
    {
        // tile 0 -> buf 0
#pragma unroll
        for (int i = 0; i < 4; i++) {
            int key = i * 16 + kv_key;
            int kg  = key;               // kbase = 0
            bool vd = kg < N1;
            const float* base = qkv_b + (size_t)(vd ? kg : 0) * H3 + h * 64 + kv_d0;
            cp16(smem_u32(&Ks0[key * KSP + kv_d0]), base + 512,  vd);
            cp16(smem_u32(&Vs0[key * VSP + kv_d0]), base + 1024, vd);
        }
        cp_commit();
    }

    const int row0g = qbase + wq + r;
    const int row1g = row0g + 8;
    const bool q0pad = row0g >= len1;
    const bool q1pad = row1g >= len1;
    const int psrc0 = (lane & 28) + (j >> 1);   // shfl source lanes (constant)
    const int psrc1 = psrc0 + 2;
    const bool podd = (j & 1);

    float oacc[8][4];
#pragma unroll
    for (int nt = 0; nt < 8; nt++)
#pragma unroll
        for (int q = 0; q < 4; q++) oacc[nt][q] = 0.f;
    float m0 = -1e30f, m1 = -1e30f, l0 = 0.f, l1 = 0.f;

    for (int kt = 0; kt < NKT; kt++) {
        const int kbase = kt * 64;
        cp_wait0();
        __syncthreads();   // K/V[kt] visible; all prior reads of the other buffer done

        const float* Ksp = (kt & 1) ? Ks1 : Ks0;
        const float* Vsp = (kt & 1) ? Vs1 : Vs0;

        if (kt + 1 < NKT) {
            const int nb = (kt + 1) * 64;
            float* Kd = (kt & 1) ? Ks0 : Ks1;
            float* Vd = (kt & 1) ? Vs0 : Vs1;
#pragma unroll
            for (int i = 0; i < 4; i++) {
                int key = i * 16 + kv_key;
                int kg  = nb + key;
                bool vd = kg < N1;
                const float* base = qkv_b + (size_t)(vd ? kg : 0) * H3 + h * 64 + kv_d0;
                cp16(smem_u32(&Kd[key * KSP + kv_d0]), base + 512,  vd);
                cp16(smem_u32(&Vd[key * VSP + kv_d0]), base + 1024, vd);
            }
            cp_commit();
        }

        // ---- S = Q K^T ----
        float sacc[8][4];
#pragma unroll
        for (int nt = 0; nt < 8; nt++)
#pragma unroll
            for (int q = 0; q < 4; q++) sacc[nt][q] = 0.f;
#pragma unroll
        for (int kk = 0; kk < 64; kk += 8) {
            uint32_t af[4];
            af[0] = __float_as_uint(Qs[(wq + r    ) * ATP + kk + j    ]);
            af[1] = __float_as_uint(Qs[(wq + r + 8) * ATP + kk + j    ]);
            af[2] = __float_as_uint(Qs[(wq + r    ) * ATP + kk + j + 4]);
            af[3] = __float_as_uint(Qs[(wq + r + 8) * ATP + kk + j + 4]);
#pragma unroll
            for (int nt = 0; nt < 8; nt++) {
                uint32_t b0 = __float_as_uint(Ksp[(nt * 8 + r) * KSP + kk + j    ]);
                uint32_t b1 = __float_as_uint(Ksp[(nt * 8 + r) * KSP + kk + j + 4]);
                mma8(sacc[nt], af, b0, b1);
            }
        }

        // ---- scale + mask (fast path when whole tile valid & unmasked) ----
        if (kbase + 64 <= len1) {
#pragma unroll
            for (int nt = 0; nt < 8; nt++)
#pragma unroll
                for (int q = 0; q < 4; q++) sacc[nt][q] *= ATT_SCALE;
        } else {
#pragma unroll
            for (int nt = 0; nt < 8; nt++) {
#pragma unroll
                for (int cc = 0; cc < 2; cc++) {
                    int kg = kbase + nt * 8 + 2 * j + cc;
                    bool kinv = (kg >= N1);
                    bool kpad = (kg >= len1);
                    sacc[nt][cc]     = (kinv || (q0pad && kpad)) ? -1e30f : sacc[nt][cc]     * ATT_SCALE;
                    sacc[nt][2 + cc] = (kinv || (q1pad && kpad)) ? -1e30f : sacc[nt][2 + cc] * ATT_SCALE;
                }
            }
        }

        // ---- online softmax (warp-local, 4-lane row groups) ----
        float mx0 = -1e30f, mx1 = -1e30f;
#pragma unroll
        for (int nt = 0; nt < 8; nt++) {
            mx0 = fmaxf(mx0, fmaxf(sacc[nt][0], sacc[nt][1]));
            mx1 = fmaxf(mx1, fmaxf(sacc[nt][2], sacc[nt][3]));
        }
        mx0 = fmaxf(mx0, __shfl_xor_sync(0xffffffffu, mx0, 1));
        mx0 = fmaxf(mx0, __shfl_xor_sync(0xffffffffu, mx0, 2));
        mx1 = fmaxf(mx1, __shfl_xor_sync(0xffffffffu, mx1, 1));
        mx1 = fmaxf(mx1, __shfl_xor_sync(0xffffffffu, mx1, 2));
        float mn0 = fmaxf(m0, mx0), mn1 = fmaxf(m1, mx1);
        float f0 = __expf(m0 - mn0), f1 = __expf(m1 - mn1);
        m0 = mn0; m1 = mn1;
        float s0 = 0.f, s1 = 0.f;
#pragma unroll
        for (int nt = 0; nt < 8; nt++) {
#pragma unroll
            for (int cc = 0; cc < 2; cc++) {
                float p0 = __expf(sacc[nt][cc]     - m0);
                float p1 = __expf(sacc[nt][2 + cc] - m1);
                sacc[nt][cc] = p0;  sacc[nt][2 + cc] = p1;
                s0 += p0; s1 += p1;
            }
        }
        s0 += __shfl_xor_sync(0xffffffffu, s0, 1);
        s0 += __shfl_xor_sync(0xffffffffu, s0, 2);
        s1 += __shfl_xor_sync(0xffffffffu, s1, 1);
        s1 += __shfl_xor_sync(0xffffffffu, s1, 2);
        l0 = l0 * f0 + s0;
        l1 = l1 * f1 + s1;
#pragma unroll
        for (int nt = 0; nt < 8; nt++) {
            oacc[nt][0] *= f0; oacc[nt][1] *= f0;
            oacc[nt][2] *= f1; oacc[nt][3] *= f1;
        }

        // ---- PV: P a-frags via warp shuffles (no smem round-trip) ----
#pragma unroll
        for (int kk = 0; kk < 64; kk += 8) {
            const int np = kk >> 3;
            float t0 = sacc[np][0], t1 = sacc[np][1];
            float t2 = sacc[np][2], t3 = sacc[np][3];
            float s00 = __shfl_sync(0xffffffffu, t0, psrc0);
            float s10 = __shfl_sync(0xffffffffu, t1, psrc0);
            float s02 = __shfl_sync(0xffffffffu, t2, psrc0);
            float s12 = __shfl_sync(0xffffffffu, t3, psrc0);
            float s01 = __shfl_sync(0xffffffffu, t0, psrc1);
            float s11 = __shfl_sync(0xffffffffu, t1, psrc1);
            float s03 = __shfl_sync(0xffffffffu, t2, psrc1);
            float s13 = __shfl_sync(0xffffffffu, t3, psrc1);
            uint32_t af[4];
            af[0] = __float_as_uint(podd ? s10 : s00);   // P[r   ][kk+j]
            af[1] = __float_as_uint(podd ? s12 : s02);   // P[r+8 ][kk+j]
            af[2] = __float_as_uint(podd ? s11 : s01);   // P[r   ][kk+j+4]
            af[3] = __float_as_uint(podd ? s13 : s03);   // P[r+8 ][kk+j+4]
#pragma unroll
            for (int nt = 0; nt < 8; nt++) {
                uint32_t b0 = __float_as_uint(Vsp[(kk + j    ) * VSP + nt * 8 + r]);
                uint32_t b1 = __float_as_uint(Vsp[(kk + j + 4) * VSP + nt * 8 + r]);
                mma8(oacc[nt], af, b0, b1);
            }
        }
    }

    // ---- normalize + write O ----
    float inv0 = 1.f / l0, inv1 = 1.f / l1;
    float* ob = o + (size_t)b * N1 * DIM + h * 64;
    if (row0g < N1) {
#pragma unroll
        for (int nt = 0; nt < 8; nt++)
            *(float2*)&ob[(size_t)row0g * DIM + nt * 8 + 2 * j] =
                make_float2(oacc[nt][0] * inv0, oacc[nt][1] * inv0);
    }
    if (row1g < N1) {
#pragma unroll
        for (int nt = 0; nt < 8; nt++)
            *(float2*)&ob[(size_t)row1g * DIM + nt * 8 + 2 * j] =
                make_float2(oacc[nt][2] * inv1, oacc[nt][3] * inv1);
    }
}

// ---------------- final LN + classifier head (cls token only) ----------------
__global__ __launch_bounds__(256) void head_kernel(
    const float* __restrict__ x, const float* __restrict__ g,
    const float* __restrict__ bb, const float* __restrict__ hw,
    const float* __restrict__ hb, float* __restrict__ out)
{
    const int b = blockIdx.x;
    const float* xr = x + (size_t)b * N1 * DIM;
    float v[2];
    float s = 0.f, s2 = 0.f;
#pragma unroll
    for (int it = 0; it < 2; it++) {
        v[it] = xr[threadIdx.x + it * 256];
        s += v[it]; s2 += v[it] * v[it];
    }
#pragma unroll
    for (int off = 16; off; off >>= 1) {
        s  += __shfl_xor_sync(0xffffffffu, s,  off);
        s2 += __shfl_xor_sync(0xffffffffu, s2, off);
    }
    __shared__ float rs[8], rs2[8];
    __shared__ float smean, srstd;
    const int w = threadIdx.x >> 5;
    if ((threadIdx.x & 31) == 0) { rs[w] = s; rs2[w] = s2; }
    __syncthreads();
    if (threadIdx.x == 0) {
        float a = 0.f, a2 = 0.f;
        for (int i = 0; i < 8; i++) { a += rs[i]; a2 += rs2[i]; }
        float mean = a * (1.f / DIM);
        float var  = a2 * (1.f / DIM) - mean * mean;
        smean = mean;
        srstd = rsqrtf(var + 1e-5f);
    }
    __syncthreads();
    const float mean = smean, rstd = srstd;

    float d0 = 0.f, d1 = 0.f;
#pragma unroll
    for (int it = 0; it < 2; it++) {
        int c = threadIdx.x + it * 256;
        float xn = (v[it] - mean) * rstd * g[c] + bb[c];
        d0 += xn * hw[2 * c + 0];
        d1 += xn * hw[2 * c + 1];
    }
#pragma unroll
    for (int off = 16; off; off >>= 1) {
        d0 += __shfl_xor_sync(0xffffffffu, d0, off);
        d1 += __shfl_xor_sync(0xffffffffu, d1, off);
    }
    __syncthreads();
    if ((threadIdx.x & 31) == 0) { rs[w] = d0; rs2[w] = d1; }
    __syncthreads();
    if (threadIdx.x == 0) {
        float a0 = 0.f, a1 = 0.f;
        for (int i = 0; i < 8; i++) { a0 += rs[i]; a1 += rs2[i]; }
        out[b * 2 + 0] = a0 + hb[0];
        out[b * 2 + 1] = a1 + hb[1];
    }
}

// ---------------- launch ----------------
extern "C" void kernel_launch(void* const* d_in, const int* in_sizes, int n_in,
                              void* d_out, int out_size)
{
    const float* x      = (const float*)d_in[0];
    const int*   lens   = (const int*)  d_in[1];
    const float* cls    = (const float*)d_in[2];
    const float* fc_w   = (const float*)d_in[3];
    const float* fc_b   = (const float*)d_in[4];
    const float* ln1_g  = (const float*)d_in[5];
    const float* ln1_b  = (const float*)d_in[6];
    const float* qkv_w  = (const float*)d_in[7];
    const float* out_w  = (const float*)d_in[8];
    const float* out_b  = (const float*)d_in[9];
    const float* ln2_g  = (const float*)d_in[10];
    const float* ln2_b  = (const float*)d_in[11];
    const float* ff1_w  = (const float*)d_in[12];
    const float* ff1_b  = (const float*)d_in[13];
    const float* ff2_w  = (const float*)d_in[14];
    const float* ff2_b  = (const float*)d_in[15];
    const float* lnf_g  = (const float*)d_in[16];
    const float* lnf_b  = (const float*)d_in[17];
    const float* head_w = (const float*)d_in[18];
    const float* head_b = (const float*)d_in[19];
    float* out = (float*)d_out;

    float *gx, *gxn, *gqkv, *go, *gh;
    cudaGetSymbolAddress((void**)&gx,   g_x);
    cudaGetSymbolAddress((void**)&gxn,  g_xn);
    cudaGetSymbolAddress((void**)&gqkv, g_qkv);
    cudaGetSymbolAddress((void**)&go,   g_o);
    cudaGetSymbolAddress((void**)&gh,   g_h);

    cudaFuncSetAttribute(sgemm_tf32, cudaFuncAttributeMaxDynamicSharedMemorySize, GEMM_SMEM);
    cudaFuncSetAttribute(attn_tf32,  cudaFuncAttributeMaxDynamicSharedMemorySize, ATT_SMEM);

    // cls rows
    cls_fill_kernel<<<BATCH, DIM>>>(cls, gx);

    // fc + GELU, remapped into cls-offset layout: M=8192, N=512, K=768
    sgemm_tf32<<<dim3(DIM / 64, (BATCH * NTOK + 127) / 128), 256, GEMM_SMEM>>>(
        x, fc_w, fc_b, nullptr, gx, BATCH * NTOK, DIM, DIN, /*mode=*/2, /*remap=*/1);

    const int gy = (ROWS_TOT + 127) / 128;   // 65
    for (int l = 0; l < DEPTH; l++) {
        ln_kernel<<<ROWS_TOT, 256>>>(gx, ln1_g + l * DIM, ln1_b + l * DIM, gxn);
        sgemm_tf32<<<dim3(H3 / 64, gy), 256, GEMM_SMEM>>>(
            gxn, qkv_w + (size_t)l * DIM * H3, nullptr, nullptr, gqkv,
            ROWS_TOT, H3, DIM, 0, 0);
        attn_tf32<<<dim3((N1 + 127) / 128, 8, BATCH), 256, ATT_SMEM>>>(gqkv, lens, go);
        sgemm_tf32<<<dim3(DIM / 64, gy), 256, GEMM_SMEM>>>(
            go, out_w + (size_t)l * DIM * DIM, out_b + l * DIM, gx, gx,
            ROWS_TOT, DIM, DIM, 3, 0);
        ln_kernel<<<ROWS_TOT, 256>>>(gx, ln2_g + l * DIM, ln2_b + l * DIM, gxn);
        sgemm_tf32<<<dim3(DIM / 64, gy), 256, GEMM_SMEM>>>(
            gxn, ff1_w + (size_t)l * DIM * DIM, ff1_b + l * DIM, nullptr, gh,
            ROWS_TOT, DIM, DIM, 2, 0);
        sgemm_tf32<<<dim3(DIM / 64, gy), 256, GEMM_SMEM>>>(
            gh, ff2_w + (size_t)l * DIM * DIM, ff2_b + l * DIM, gx, gx,
            ROWS_TOT, DIM, DIM, 3, 0);
    }

    head_kernel<<<BATCH, 256>>>(gx, lnf_g, lnf_b, head_w, head_b, out);
}